// round 13
// baseline (speedup 1.0000x reference)
#include <cuda_runtime.h>
#include <cuda_bf16.h>
#include <math.h>
#include <stdint.h>

#define HID   3584
#define NH    28
#define NKV   4
#define HD    128
#define INTER 18944
#define BS    64
#define BLOCK 16
#define MAX_BLOCKS 128
#define GROUP 7   // NH / NKV

// ---------------- scratch (device globals; no allocation allowed) ----------
__device__ float g_h[BS * HID];
__device__ float g_q[BS * NH * HD];
__device__ float g_k[BS * NKV * HD];
__device__ float g_v[BS * NKV * HD];
__device__ float g_knew[BS * NKV * HD];
__device__ float g_vnew[BS * NKV * HD];
__device__ float g_attn[BS * NH * HD];
__device__ float g_hidden[BS * HID];
__device__ float g_h2[BS * HID];
__device__ float g_gate[BS * INTER];
__device__ float g_act[BS * INTER];
__device__ float g_pQ[8 * BS * HID];
__device__ float g_pK[8 * BS * NKV * HD];
__device__ float g_pV[8 * BS * NKV * HD];
__device__ float g_pO[8 * BS * HID];
__device__ float g_pD[8 * BS * HID];
// attention partials: [split][b][kvh][group][hd]
__device__ float g_attP[2 * BS * NKV * GROUP * HD];
__device__ float g_attM[2 * BS * NKV * GROUP];
__device__ float g_attL[2 * BS * NKV * GROUP];

// ---------------- helpers ---------------------------------------------------
__device__ __forceinline__ void ldsm4(uint32_t& r0, uint32_t& r1, uint32_t& r2, uint32_t& r3,
                                      uint32_t addr)
{
    asm volatile("ldmatrix.sync.aligned.m8n8.x4.shared.b16 {%0,%1,%2,%3}, [%4];"
                 : "=r"(r0), "=r"(r1), "=r"(r2), "=r"(r3) : "r"(addr));
}

__device__ __forceinline__ void mma16816(float* c, const uint32_t* a, uint32_t b0, uint32_t b1)
{
    asm volatile("mma.sync.aligned.m16n8k16.row.col.f32.bf16.bf16.f32 "
                 "{%0,%1,%2,%3}, {%4,%5,%6,%7}, {%8,%9}, {%0,%1,%2,%3};"
                 : "+f"(c[0]), "+f"(c[1]), "+f"(c[2]), "+f"(c[3])
                 : "r"(a[0]), "r"(a[1]), "r"(a[2]), "r"(a[3]), "r"(b0), "r"(b1));
}

__device__ __forceinline__ uint32_t packbf2(__nv_bfloat16 a, __nv_bfloat16 b)
{
    __nv_bfloat162 t = __halves2bfloat162(a, b);
    uint32_t u; memcpy(&u, &t, 4); return u;
}

// split a float4 into hi/lo bf16 quads, store as 8B each
__device__ __forceinline__ void split4_store(float4 v, __nv_bfloat16* hp, __nv_bfloat16* lp)
{
    __nv_bfloat16 h0 = __float2bfloat16_rn(v.x), h1 = __float2bfloat16_rn(v.y);
    __nv_bfloat16 h2 = __float2bfloat16_rn(v.z), h3 = __float2bfloat16_rn(v.w);
    __nv_bfloat16 l0 = __float2bfloat16_rn(v.x - __bfloat162float(h0));
    __nv_bfloat16 l1 = __float2bfloat16_rn(v.y - __bfloat162float(h1));
    __nv_bfloat16 l2 = __float2bfloat16_rn(v.z - __bfloat162float(h2));
    __nv_bfloat16 l3 = __float2bfloat16_rn(v.w - __bfloat162float(h3));
    uint2 hu; hu.x = packbf2(h0, h1); hu.y = packbf2(h2, h3);
    uint2 lu; lu.x = packbf2(l0, l1); lu.y = packbf2(l2, l3);
    *(uint2*)hp = hu;
    *(uint2*)lp = lu;
}

__device__ __forceinline__ void cp16(uint32_t dst, const void* src)
{
    asm volatile("cp.async.cg.shared.global [%0], [%1], 16;" :: "r"(dst), "l"(src));
}
#define CP_COMMIT() asm volatile("cp.async.commit_group;")
#define CP_WAIT_ALL() asm volatile("cp.async.wait_group 0;")

// ---------------- RMSNorm ---------------------------------------------------
__global__ __launch_bounds__(256) void rmsnorm_kernel(const float* __restrict__ x,
                                                      const float* __restrict__ w,
                                                      float* __restrict__ out)
{
    int b = blockIdx.x, t = threadIdx.x;
    const float4* x4 = (const float4*)(x + b * HID);
    const float4* w4 = (const float4*)w;
    float4* o4 = (float4*)(out + b * HID);

    float ss = 0.f;
    for (int i = t; i < HID / 4; i += 256) {
        float4 v = x4[i];
        ss += v.x * v.x + v.y * v.y + v.z * v.z + v.w * v.w;
    }
    #pragma unroll
    for (int o = 16; o; o >>= 1) ss += __shfl_xor_sync(0xffffffffu, ss, o);

    __shared__ float red[8];
    __shared__ float s_rs;
    if ((t & 31) == 0) red[t >> 5] = ss;
    __syncthreads();
    if (t == 0) {
        float tot = 0.f;
        for (int i = 0; i < 8; i++) tot += red[i];
        s_rs = rsqrtf(tot / (float)HID + 1e-6f);
    }
    __syncthreads();
    float rs = s_rs;
    for (int i = t; i < HID / 4; i += 256) {
        float4 v = x4[i], ww = w4[i];
        float4 o;
        o.x = v.x * rs * ww.x; o.y = v.y * rs * ww.y;
        o.z = v.z * rs * ww.z; o.w = v.w * rs * ww.w;
        o4[i] = o;
    }
}

// ---------------- split-bf16 3-pass ldmatrix MMA GEMM (KC=64) ---------------
// out[by][64, N] = A[64, koff:+Kchunk] @ W[nb:nb+NTILE, koff:+Kchunk]^T
// 8 warps: m-half (w&1) -> 32 rows, n-quarter (w>>1) -> NTILE/4 cols.
// ROW=72 bf16 (144B): ldmatrix 8-row groups hit all 32 banks exactly once.
// ldmatrix.x4 on B: r0=(n+0,k0-7) r1=(n+8,k0-7) r2=(n+0,k8-15) r3=(n+8,k8-15);
// mma B pairs are (r0,r2) and (r1,r3).
enum { EPI_NONE = 0, EPI_SILU = 3 };

template<int NTILE, int EPI>
__global__ __launch_bounds__(256, 1) void mma_gemm(const float* __restrict__ A,
                                                   const float* __restrict__ W,
                                                   const float* __restrict__ aux,
                                                   float* __restrict__ out,
                                                   int N, int K, int Kchunk)
{
    constexpr int KC    = 64;
    constexpr int ROW   = 72;
    constexpr int NSUB  = NTILE / 32;
    constexpr int NPAIR = NSUB / 2;
    constexpr int ALD   = 4;             // A float4 loads per thread
    constexpr int BLD   = NTILE / 16;    // B float4 loads per thread
    constexpr int ABUF  = 64 * ROW * 2;      // bytes per A buffer
    constexpr int BBUF  = NTILE * ROW * 2;   // bytes per B buffer

    extern __shared__ __align__(16) char dynsm[];
    __nv_bfloat16* Ah = (__nv_bfloat16*)dynsm;            // [2][64][ROW]
    __nv_bfloat16* Al = Ah + 2 * 64 * ROW;
    __nv_bfloat16* Bh = Al + 2 * 64 * ROW;                // [2][NTILE][ROW]
    __nv_bfloat16* Bl = Bh + 2 * NTILE * ROW;

    const int t    = threadIdx.x;
    const int nb   = blockIdx.x * NTILE;
    const int koff = blockIdx.y * Kchunk;
    const int w    = t >> 5, l = t & 31;
    const int g    = l >> 2, tg = l & 3;
    const int mh   = w & 1, nq = w >> 1;
    const int grp  = l >> 3, rr = l & 7;

    // loader: thread covers rows lr+16j with 4 consecutive k at lc
    const int lr = t >> 4;
    const int lc = (t & 15) * 4;

    float acc[2][NSUB][4];
    #pragma unroll
    for (int ms = 0; ms < 2; ms++)
        #pragma unroll
        for (int s = 0; s < NSUB; s++)
            #pragma unroll
            for (int i = 0; i < 4; i++) acc[ms][s][i] = 0.f;

    const uint32_t aB  = (uint32_t)__cvta_generic_to_shared(Ah);
    const uint32_t alB = (uint32_t)__cvta_generic_to_shared(Al);
    const uint32_t bB  = (uint32_t)__cvta_generic_to_shared(Bh);
    const uint32_t blB = (uint32_t)__cvta_generic_to_shared(Bl);
    const int acol = (grp >> 1) * 8;
    uint32_t aAddr[2], alAddr[2], bAddr[NPAIR], blAddr[NPAIR];
    #pragma unroll
    for (int ms = 0; ms < 2; ms++) {
        int row = mh * 32 + ms * 16 + (grp & 1) * 8 + rr;
        aAddr[ms]  = aB  + (row * ROW + acol) * 2;
        alAddr[ms] = alB + (row * ROW + acol) * 2;
    }
    #pragma unroll
    for (int p = 0; p < NPAIR; p++) {
        int row = nq * (NTILE / 4) + p * 16 + (grp & 1) * 8 + rr;
        bAddr[p]  = bB  + (row * ROW + acol) * 2;
        blAddr[p] = blB + (row * ROW + acol) * 2;
    }

    const float* Ap = A + koff;
    const float* Wp = W + koff;
    const int niter = Kchunk / KC;

    float4 pa[ALD], pb[BLD];
    #pragma unroll
    for (int j = 0; j < ALD; j++)
        pa[j] = *(const float4*)(Ap + (size_t)(lr + 16 * j) * K + lc);
    #pragma unroll
    for (int j = 0; j < BLD; j++)
        pb[j] = *(const float4*)(Wp + (size_t)(nb + lr + 16 * j) * K + lc);

    int cur = 0;
    for (int c = 0; c < niter; c++) {
        #pragma unroll
        for (int j = 0; j < ALD; j++)
            split4_store(pa[j], &Ah[(cur * 64 + lr + 16 * j) * ROW + lc],
                                &Al[(cur * 64 + lr + 16 * j) * ROW + lc]);
        #pragma unroll
        for (int j = 0; j < BLD; j++)
            split4_store(pb[j], &Bh[(cur * NTILE + lr + 16 * j) * ROW + lc],
                                &Bl[(cur * NTILE + lr + 16 * j) * ROW + lc]);
        __syncthreads();

        if (c + 1 < niter) {
            int kb = (c + 1) * KC;
            #pragma unroll
            for (int j = 0; j < ALD; j++)
                pa[j] = *(const float4*)(Ap + (size_t)(lr + 16 * j) * K + kb + lc);
            #pragma unroll
            for (int j = 0; j < BLD; j++)
                pb[j] = *(const float4*)(Wp + (size_t)(nb + lr + 16 * j) * K + kb + lc);
        }

        const uint32_t oa = cur * ABUF, ob = cur * BBUF;
        #pragma unroll
        for (int kk = 0; kk < KC; kk += 16) {
            uint32_t ah[2][4], al_[2][4];
            #pragma unroll
            for (int ms = 0; ms < 2; ms++) {
                ldsm4(ah[ms][0], ah[ms][1], ah[ms][2], ah[ms][3], aAddr[ms] + oa + kk * 2);
                ldsm4(al_[ms][0], al_[ms][1], al_[ms][2], al_[ms][3], alAddr[ms] + oa + kk * 2);
            }
            #pragma unroll
            for (int p = 0; p < NPAIR; p++) {
                uint32_t bh[4], bl_[4];
                ldsm4(bh[0], bh[1], bh[2], bh[3], bAddr[p] + ob + kk * 2);
                ldsm4(bl_[0], bl_[1], bl_[2], bl_[3], blAddr[p] + ob + kk * 2);
                #pragma unroll
                for (int ms = 0; ms < 2; ms++) {
                    mma16816(acc[ms][2 * p],     ah[ms],  bh[0],  bh[2]);
                    mma16816(acc[ms][2 * p],     ah[ms],  bl_[0], bl_[2]);
                    mma16816(acc[ms][2 * p],     al_[ms], bh[0],  bh[2]);
                    mma16816(acc[ms][2 * p + 1], ah[ms],  bh[1],  bh[3]);
                    mma16816(acc[ms][2 * p + 1], ah[ms],  bl_[1], bl_[3]);
                    mma16816(acc[ms][2 * p + 1], al_[ms], bh[1],  bh[3]);
                }
            }
        }
        cur ^= 1;
    }

    float* outp = out + (size_t)blockIdx.y * 64 * N;
    #pragma unroll
    for (int ms = 0; ms < 2; ms++) {
        #pragma unroll
        for (int s = 0; s < NSUB; s++) {
            const int r0 = mh * 32 + ms * 16 + g;
            const int r1 = r0 + 8;
            const int col = nb + nq * (NTILE / 4) + s * 8 + tg * 2;
            const int rws[4] = {r0, r0, r1, r1};
            const int cls[4] = {col, col + 1, col, col + 1};
            #pragma unroll
            for (int i = 0; i < 4; i++) {
                float o = acc[ms][s][i];
                if constexpr (EPI == EPI_SILU) {
                    float gv = aux[(size_t)rws[i] * N + cls[i]];
                    o *= gv / (1.f + expf(-gv));
                }
                outp[(size_t)rws[i] * N + cls[i]] = o;
            }
        }
    }
}

// ---------------- split-K reduce --------------------------------------------
enum { RED_NONE = 0, RED_BIAS = 1, RED_RESID = 2 };

template<int SK, int MODE>
__global__ __launch_bounds__(256) void reduce_kernel(const float* __restrict__ part,
                                                     const float* __restrict__ extra,
                                                     float* __restrict__ out,
                                                     int total, int N)
{
    int i = blockIdx.x * 256 + threadIdx.x;
    if (i >= total) return;
    float s = 0.f;
    #pragma unroll
    for (int k = 0; k < SK; k++) s += part[(size_t)k * total + i];
    if constexpr (MODE == RED_BIAS)  s += extra[i % N];
    if constexpr (MODE == RED_RESID) s += extra[i];
    out[i] = s;
}

// ---------------- RoPE (double-precision angles) ----------------------------
__global__ __launch_bounds__(256) void rope_kernel(float* __restrict__ q,
                                                   const float* __restrict__ k,
                                                   const float* __restrict__ v,
                                                   const int* __restrict__ positions,
                                                   float* __restrict__ knew,
                                                   float* __restrict__ vnew)
{
    int b = blockIdx.x, t = threadIdx.x;
    double pos = (double)positions[b];
    const double L = 13.815510557964274104107948728106; // ln(1e6)

    for (int i = t; i < NH * 64; i += 256) {
        int h = i >> 6, d = i & 63;
        double inv = exp(-(double)(2 * d) * (1.0 / HD) * L);
        double cd, sd; sincos(pos * inv, &cd, &sd);
        float c = (float)cd, s = (float)sd;
        float* base = q + b * NH * HD + h * HD + d;
        float t1 = base[0], t2 = base[64];
        base[0]  = t1 * c - t2 * s;
        base[64] = t2 * c + t1 * s;
    }
    for (int i = t; i < NKV * 64; i += 256) {
        int h = i >> 6, d = i & 63;
        double inv = exp(-(double)(2 * d) * (1.0 / HD) * L);
        double cd, sd; sincos(pos * inv, &cd, &sd);
        float c = (float)cd, s = (float)sd;
        const float* src = k + b * NKV * HD + h * HD + d;
        float t1 = src[0], t2 = src[64];
        float* dst = knew + b * NKV * HD + h * HD + d;
        dst[0]  = t1 * c - t2 * s;
        dst[64] = t2 * c + t1 * s;
    }
    for (int i = t; i < NKV * HD; i += 256)
        vnew[b * NKV * HD + i] = v[b * NKV * HD + i];
}

// ---------------- Paged attention (KV-split x2, online softmax) -------------
// Scores: warp w < 7 owns head w (lane = token).  P.V: dim-sliced — warp w
// owns dims [16w,16w+16) for ALL heads; lane = (head l>>2, dim-quad l&3).
// Each (kvh, b, split) CTA covers half the tiles; writes unnormalized acc
// plus (m, l); a merge kernel combines the two splits.  Input caches are
// never mutated: the new token (tok == pos) is substituted from knew/vnew.
__global__ __launch_bounds__(256, 1) void attn_kernel(const float* __restrict__ kc,
                                                      const float* __restrict__ vc,
                                                      const int* __restrict__ block_tables,
                                                      const int* __restrict__ seq_lens,
                                                      const float* __restrict__ qbuf,
                                                      const float* __restrict__ knew,
                                                      const float* __restrict__ vnew,
                                                      float* __restrict__ partP,
                                                      float* __restrict__ partM,
                                                      float* __restrict__ partL)
{
    const int kvh = blockIdx.x, b = blockIdx.y, split = blockIdx.z;
    const int t = threadIdx.x;
    const int seq = seq_lens[b];
    const int pos = seq - 1;

    const int ntiles = (seq + 31) >> 5;
    const int half = (ntiles + 1) >> 1;
    const int t0 = split ? half : 0;
    const int t1 = split ? ntiles : half;

    extern __shared__ __align__(16) char dynsm[];
    float* q_s = (float*)dynsm;                 // [GROUP][HD]
    float* k_s = q_s + GROUP * HD;              // [2][32][132]
    float* v_s = k_s + 2 * 32 * 132;            // [2][32][132]
    __shared__ int bt_s[MAX_BLOCKS];
    __shared__ float p_s[GROUP][32];
    __shared__ float m_s[GROUP], l_s[GROUP], sc_s[GROUP];

    const uint32_t kBase = (uint32_t)__cvta_generic_to_shared(k_s);
    const uint32_t vBase = (uint32_t)__cvta_generic_to_shared(v_s);

    for (int i = t; i < MAX_BLOCKS; i += 256) bt_s[i] = block_tables[b * MAX_BLOCKS + i];
    for (int i = t; i < GROUP * HD; i += 256)
        q_s[i] = qbuf[b * NH * HD + kvh * GROUP * HD + i];
    if (t < GROUP) { m_s[t] = -1e30f; l_s[t] = 0.f; }
    __syncthreads();

    const int w = t >> 5, lane = t & 31;
    const int hh = lane >> 2, dq = lane & 3;
    const int hsel = hh < GROUP ? hh : GROUP - 1;
    const int dpv = w * 16 + dq * 4;
    float acc[4] = {0.f, 0.f, 0.f, 0.f};

    auto issue_tile = [&](int tile, int buf) {
        const int tbase = tile << 5;
        #pragma unroll
        for (int j = 0; j < 4; j++) {
            int i = t + 256 * j;
            int tt = i >> 5, d4 = (i & 31) << 2;
            int tok = tbase + tt;
            const float *ksrc, *vsrc;
            if (tok == pos) {
                int off = b * NKV * HD + kvh * HD + d4;
                ksrc = knew + off; vsrc = vnew + off;
            } else {
                int blk = bt_s[tok >> 4];
                int base = ((blk << 4) + (tok & 15)) * (NKV * HD) + kvh * HD + d4;
                ksrc = kc + base; vsrc = vc + base;
            }
            uint32_t soff = ((buf * 32 + tt) * 132 + d4) * 4;
            cp16(kBase + soff, ksrc);
            cp16(vBase + soff, vsrc);
        }
        CP_COMMIT();
    };

    issue_tile(t0, 0);
    int cur = 0;

    for (int tile = t0; tile < t1; tile++) {
        CP_WAIT_ALL();
        __syncthreads();
        if (tile + 1 < t1) issue_tile(tile + 1, cur ^ 1);

        const int tbase = tile << 5;
        const float* kb = k_s + cur * 32 * 132;
        const float* vb = v_s + cur * 32 * 132;

        if (w < GROUP) {
            float sc = 0.f;
            #pragma unroll
            for (int d4 = 0; d4 < HD; d4 += 4) {
                float4 qv = *(const float4*)&q_s[w * HD + d4];
                float4 kv = *(const float4*)&kb[lane * 132 + d4];
                sc = fmaf(qv.x, kv.x, sc); sc = fmaf(qv.y, kv.y, sc);
                sc = fmaf(qv.z, kv.z, sc); sc = fmaf(qv.w, kv.w, sc);
            }
            sc *= 0.08838834764831845f;            // HD^-0.5
            if (tbase + lane >= seq) sc = -1e30f;

            float mx = sc;
            #pragma unroll
            for (int o = 16; o; o >>= 1) mx = fmaxf(mx, __shfl_xor_sync(0xffffffffu, mx, o));
            float m_old = m_s[w];
            float m_new = fmaxf(m_old, mx);
            float p = expf(sc - m_new);
            p_s[w][lane] = p;
            float sum = p;
            #pragma unroll
            for (int o = 16; o; o >>= 1) sum += __shfl_xor_sync(0xffffffffu, sum, o);
            if (lane == 0) {
                float scl = expf(m_old - m_new);
                sc_s[w] = scl;
                l_s[w] = l_s[w] * scl + sum;
                m_s[w] = m_new;
            }
        }
        __syncthreads();

        // P.V: all 8 warps; V tile read exactly once across the CTA
        {
            float scl = sc_s[hsel];
            acc[0] *= scl; acc[1] *= scl; acc[2] *= scl; acc[3] *= scl;
            #pragma unroll 8
            for (int tt = 0; tt < 32; tt++) {
                float p = p_s[hsel][tt];
                float4 v4 = *(const float4*)&vb[tt * 132 + dpv];
                acc[0] = fmaf(p, v4.x, acc[0]);
                acc[1] = fmaf(p, v4.y, acc[1]);
                acc[2] = fmaf(p, v4.z, acc[2]);
                acc[3] = fmaf(p, v4.w, acc[3]);
            }
        }
        __syncthreads();
        cur ^= 1;
    }

    if (hh < GROUP) {
        size_t base = ((((size_t)split * BS + b) * NKV + kvh) * GROUP + hh) * HD + dpv;
        float4 o; o.x = acc[0]; o.y = acc[1]; o.z = acc[2]; o.w = acc[3];
        *(float4*)(partP + base) = o;
        if (w == 0 && dq == 0) {
            size_t mlb = (((size_t)split * BS + b) * NKV + kvh) * GROUP + hh;
            partM[mlb] = m_s[hh];
            partL[mlb] = l_s[hh];
        }
    }
}

// merge the 2 KV splits
__global__ __launch_bounds__(256) void attn_merge_kernel(const float* __restrict__ partP,
                                                         const float* __restrict__ partM,
                                                         const float* __restrict__ partL,
                                                         float* __restrict__ attn_out)
{
    const int total = BS * NKV * GROUP * HD;
    int i = blockIdx.x * 256 + threadIdx.x;
    if (i >= total) return;
    int ml = i >> 7;    // (b*NKV + kvh)*GROUP + hh
    int d  = i & 127;
    float m0 = partM[ml], m1 = partM[total / HD + ml];
    float l0 = partL[ml], l1 = partL[total / HD + ml];
    float M = fmaxf(m0, m1);
    float w0 = expf(m0 - M), w1 = expf(m1 - M);
    float denom = l0 * w0 + l1 * w1;
    float a0 = partP[i], a1 = partP[total + i];
    int b = ml / (NKV * GROUP);
    int rest = ml % (NKV * GROUP);   // kvh*GROUP + hh == head index
    attn_out[((size_t)b * NH + rest) * HD + d] = (a0 * w0 + a1 * w1) / denom;
}

// ---------------- launch ----------------------------------------------------
extern "C" void kernel_launch(void* const* d_in, const int* in_sizes, int n_in,
                              void* d_out, int out_size)
{
    const float* x            = (const float*)d_in[0];
    const int*   positions    = (const int*)  d_in[1];
    const float* k_cache      = (const float*)d_in[2];
    const float* v_cache      = (const float*)d_in[3];
    const int*   block_tables = (const int*)  d_in[4];
    const int*   seq_lens     = (const int*)  d_in[5];
    /* d_in[6] slot_mapping: unused (pos == seq_len-1 substitution instead) */
    const float* in_w   = (const float*)d_in[7];
    const float* post_w = (const float*)d_in[8];
    const float* Wq = (const float*)d_in[9];
    const float* bq = (const float*)d_in[10];
    const float* Wk = (const float*)d_in[11];
    const float* bk = (const float*)d_in[12];
    const float* Wv = (const float*)d_in[13];
    const float* bv = (const float*)d_in[14];
    const float* Wo = (const float*)d_in[15];
    const float* Wg = (const float*)d_in[16];
    const float* Wu = (const float*)d_in[17];
    const float* Wd = (const float*)d_in[18];
    float* out = (float*)d_out;

    float *p_h, *p_q, *p_k, *p_v, *p_kn, *p_vn, *p_attn, *p_hidden, *p_h2, *p_gate, *p_act;
    float *pQ, *pK, *pV, *pO, *pD, *aP, *aM, *aL;
    cudaGetSymbolAddress((void**)&p_h,      g_h);
    cudaGetSymbolAddress((void**)&p_q,      g_q);
    cudaGetSymbolAddress((void**)&p_k,      g_k);
    cudaGetSymbolAddress((void**)&p_v,      g_v);
    cudaGetSymbolAddress((void**)&p_kn,     g_knew);
    cudaGetSymbolAddress((void**)&p_vn,     g_vnew);
    cudaGetSymbolAddress((void**)&p_attn,   g_attn);
    cudaGetSymbolAddress((void**)&p_hidden, g_hidden);
    cudaGetSymbolAddress((void**)&p_h2,     g_h2);
    cudaGetSymbolAddress((void**)&p_gate,   g_gate);
    cudaGetSymbolAddress((void**)&p_act,    g_act);
    cudaGetSymbolAddress((void**)&pQ, g_pQ);
    cudaGetSymbolAddress((void**)&pK, g_pK);
    cudaGetSymbolAddress((void**)&pV, g_pV);
    cudaGetSymbolAddress((void**)&pO, g_pO);
    cudaGetSymbolAddress((void**)&pD, g_pD);
    cudaGetSymbolAddress((void**)&aP, g_attP);
    cudaGetSymbolAddress((void**)&aM, g_attM);
    cudaGetSymbolAddress((void**)&aL, g_attL);

    constexpr int SM128v = 2 * (64 + 64 + 128 + 128) * 72 * 2;   // 110592
    constexpr int SM64v  = 2 * (64 + 64 + 64 + 64) * 72 * 2;     // 73728
    constexpr int SMATT  = (GROUP * HD + 4 * 32 * 132) * 4;      // 71168

    cudaFuncSetAttribute(mma_gemm<128, EPI_NONE>, cudaFuncAttributeMaxDynamicSharedMemorySize, SM128v);
    cudaFuncSetAttribute(mma_gemm<128, EPI_SILU>, cudaFuncAttributeMaxDynamicSharedMemorySize, SM128v);
    cudaFuncSetAttribute(mma_gemm<64,  EPI_NONE>, cudaFuncAttributeMaxDynamicSharedMemorySize, SM64v);
    cudaFuncSetAttribute(attn_kernel, cudaFuncAttributeMaxDynamicSharedMemorySize, SMATT);

    rmsnorm_kernel<<<BS, 256>>>(x, in_w, p_h);

    // QKV projections (split-K 8)
    mma_gemm<128, EPI_NONE><<<dim3(NH * HD / 128, 8), 256, SM128v>>>(p_h, Wq, nullptr, pQ, NH * HD, HID, HID / 8);
    mma_gemm<64,  EPI_NONE><<<dim3(NKV * HD / 64, 8), 256, SM64v>>>(p_h, Wk, nullptr, pK, NKV * HD, HID, HID / 8);
    mma_gemm<64,  EPI_NONE><<<dim3(NKV * HD / 64, 8), 256, SM64v>>>(p_h, Wv, nullptr, pV, NKV * HD, HID, HID / 8);
    reduce_kernel<8, RED_BIAS><<<(BS * NH * HD) / 256, 256>>>(pQ, bq, p_q, BS * NH * HD, NH * HD);
    reduce_kernel<8, RED_BIAS><<<(BS * NKV * HD) / 256, 256>>>(pK, bk, p_k, BS * NKV * HD, NKV * HD);
    reduce_kernel<8, RED_BIAS><<<(BS * NKV * HD) / 256, 256>>>(pV, bv, p_v, BS * NKV * HD, NKV * HD);

    rope_kernel<<<BS, 256>>>(p_q, p_k, p_v, positions, p_kn, p_vn);

    attn_kernel<<<dim3(NKV, BS, 2), 256, SMATT>>>(k_cache, v_cache, block_tables, seq_lens,
                                                  p_q, p_kn, p_vn, aP, aM, aL);
    attn_merge_kernel<<<(BS * NKV * GROUP * HD) / 256, 256>>>(aP, aM, aL, p_attn);

    // O projection (split-K 8) + residual
    mma_gemm<128, EPI_NONE><<<dim3(HID / 128, 8), 256, SM128v>>>(p_attn, Wo, nullptr, pO, HID, NH * HD, (NH * HD) / 8);
    reduce_kernel<8, RED_RESID><<<(BS * HID) / 256, 256>>>(pO, x, p_hidden, BS * HID, HID);

    rmsnorm_kernel<<<BS, 256>>>(p_hidden, post_w, p_h2);

    // MLP: gate, up*silu(gate)  (single wave each: 148 CTAs)
    mma_gemm<128, EPI_NONE><<<dim3(INTER / 128, 1), 256, SM128v>>>(p_h2, Wg, nullptr, p_gate, INTER, HID, HID);
    mma_gemm<128, EPI_SILU><<<dim3(INTER / 128, 1), 256, SM128v>>>(p_h2, Wu, p_gate, p_act, INTER, HID, HID);

    // down projection (split-K 8) + residual
    mma_gemm<128, EPI_NONE><<<dim3(HID / 128, 8), 256, SM128v>>>(p_act, Wd, nullptr, pD, HID, INTER, INTER / 8);
    reduce_kernel<8, RED_RESID><<<(BS * HID) / 256, 256>>>(pD, p_hidden, out, BS * HID, HID);
}

// round 14
// speedup vs baseline: 1.5255x; 1.5255x over previous
#include <cuda_runtime.h>
#include <cuda_bf16.h>
#include <math.h>
#include <stdint.h>

#define HID   3584
#define NH    28
#define NKV   4
#define HD    128
#define INTER 18944
#define BS    64
#define BLOCK 16
#define MAX_BLOCKS 128
#define GROUP 7   // NH / NKV

// ---------------- scratch (device globals; no allocation allowed) ----------
__device__ float g_h[BS * HID];
__device__ float g_q[BS * NH * HD];
__device__ float g_k[BS * NKV * HD];
__device__ float g_v[BS * NKV * HD];
__device__ float g_knew[BS * NKV * HD];
__device__ float g_vnew[BS * NKV * HD];
__device__ float g_attn[BS * NH * HD];
__device__ float g_hidden[BS * HID];
__device__ float g_h2[BS * HID];
__device__ float g_gate[BS * INTER];
__device__ float g_act[BS * INTER];
__device__ float g_pQ[8 * BS * HID];
__device__ float g_pK[8 * BS * NKV * HD];
__device__ float g_pV[8 * BS * NKV * HD];
__device__ float g_pO[8 * BS * HID];
__device__ float g_pD[8 * BS * HID];
// attention partials: [split][b][kvh][group][hd]
__device__ float g_attP[2 * BS * NKV * GROUP * HD];
__device__ float g_attM[2 * BS * NKV * GROUP];
__device__ float g_attL[2 * BS * NKV * GROUP];

// ---------------- helpers ---------------------------------------------------
__device__ __forceinline__ void ldsm4(uint32_t& r0, uint32_t& r1, uint32_t& r2, uint32_t& r3,
                                      uint32_t addr)
{
    asm volatile("ldmatrix.sync.aligned.m8n8.x4.shared.b16 {%0,%1,%2,%3}, [%4];"
                 : "=r"(r0), "=r"(r1), "=r"(r2), "=r"(r3) : "r"(addr));
}

__device__ __forceinline__ void mma16816(float* c, const uint32_t* a, uint32_t b0, uint32_t b1)
{
    asm volatile("mma.sync.aligned.m16n8k16.row.col.f32.bf16.bf16.f32 "
                 "{%0,%1,%2,%3}, {%4,%5,%6,%7}, {%8,%9}, {%0,%1,%2,%3};"
                 : "+f"(c[0]), "+f"(c[1]), "+f"(c[2]), "+f"(c[3])
                 : "r"(a[0]), "r"(a[1]), "r"(a[2]), "r"(a[3]), "r"(b0), "r"(b1));
}

__device__ __forceinline__ uint32_t packbf2(__nv_bfloat16 a, __nv_bfloat16 b)
{
    __nv_bfloat162 t = __halves2bfloat162(a, b);
    uint32_t u; memcpy(&u, &t, 4); return u;
}

// split a float4 into hi/lo bf16 quads, store as 8B each
__device__ __forceinline__ void split4_store(float4 v, __nv_bfloat16* hp, __nv_bfloat16* lp)
{
    __nv_bfloat16 h0 = __float2bfloat16_rn(v.x), h1 = __float2bfloat16_rn(v.y);
    __nv_bfloat16 h2 = __float2bfloat16_rn(v.z), h3 = __float2bfloat16_rn(v.w);
    __nv_bfloat16 l0 = __float2bfloat16_rn(v.x - __bfloat162float(h0));
    __nv_bfloat16 l1 = __float2bfloat16_rn(v.y - __bfloat162float(h1));
    __nv_bfloat16 l2 = __float2bfloat16_rn(v.z - __bfloat162float(h2));
    __nv_bfloat16 l3 = __float2bfloat16_rn(v.w - __bfloat162float(h3));
    uint2 hu; hu.x = packbf2(h0, h1); hu.y = packbf2(h2, h3);
    uint2 lu; lu.x = packbf2(l0, l1); lu.y = packbf2(l2, l3);
    *(uint2*)hp = hu;
    *(uint2*)lp = lu;
}

__device__ __forceinline__ void cp16(uint32_t dst, const void* src)
{
    asm volatile("cp.async.cg.shared.global [%0], [%1], 16;" :: "r"(dst), "l"(src));
}
#define CP_COMMIT() asm volatile("cp.async.commit_group;")
#define CP_WAIT_ALL() asm volatile("cp.async.wait_group 0;")

// ---------------- RMSNorm ---------------------------------------------------
__global__ __launch_bounds__(256) void rmsnorm_kernel(const float* __restrict__ x,
                                                      const float* __restrict__ w,
                                                      float* __restrict__ out)
{
    int b = blockIdx.x, t = threadIdx.x;
    const float4* x4 = (const float4*)(x + b * HID);
    const float4* w4 = (const float4*)w;
    float4* o4 = (float4*)(out + b * HID);

    float ss = 0.f;
    for (int i = t; i < HID / 4; i += 256) {
        float4 v = x4[i];
        ss += v.x * v.x + v.y * v.y + v.z * v.z + v.w * v.w;
    }
    #pragma unroll
    for (int o = 16; o; o >>= 1) ss += __shfl_xor_sync(0xffffffffu, ss, o);

    __shared__ float red[8];
    __shared__ float s_rs;
    if ((t & 31) == 0) red[t >> 5] = ss;
    __syncthreads();
    if (t == 0) {
        float tot = 0.f;
        for (int i = 0; i < 8; i++) tot += red[i];
        s_rs = rsqrtf(tot / (float)HID + 1e-6f);
    }
    __syncthreads();
    float rs = s_rs;
    for (int i = t; i < HID / 4; i += 256) {
        float4 v = x4[i], ww = w4[i];
        float4 o;
        o.x = v.x * rs * ww.x; o.y = v.y * rs * ww.y;
        o.z = v.z * rs * ww.z; o.w = v.w * rs * ww.w;
        o4[i] = o;
    }
}

// ---------------- split-bf16 3-pass ldmatrix MMA GEMM (KC=32, verified) -----
// out[by][64, N] = A[64, koff:+Kchunk] @ W[nb:nb+NTILE, koff:+Kchunk]^T
// 8 warps: m-half (w&1) -> 32 rows, n-quarter (w>>1) -> NTILE/4 cols.
// ROW=40 bf16 (80B): ldmatrix 8-row groups hit all 32 banks exactly once.
// ldmatrix.x4 on B: r0=(n+0,k0-7) r1=(n+8,k0-7) r2=(n+0,k8-15) r3=(n+8,k8-15);
// mma B pairs are (r0,r2) and (r1,r3).
enum { EPI_NONE = 0, EPI_SILU = 3 };

template<int NTILE, int EPI>
__global__ __launch_bounds__(256, 1) void mma_gemm(const float* __restrict__ A,
                                                   const float* __restrict__ W,
                                                   const float* __restrict__ aux,
                                                   float* __restrict__ out,
                                                   int N, int K, int Kchunk)
{
    constexpr int ROW   = 40;            // padded smem row, bf16 elems (80B)
    constexpr int NSUB  = NTILE / 32;    // n8 subtiles per warp (2 or 4)
    constexpr int NPAIR = NSUB / 2;      // x4 B-loads per k-step (1 or 2)
    constexpr int BLD   = NTILE / 32;    // B float4 loads per thread per iter
    constexpr int ABUF  = 64 * ROW * 2;      // bytes per A buffer
    constexpr int BBUF  = NTILE * ROW * 2;   // bytes per B buffer

    extern __shared__ __align__(16) char dynsm[];
    __nv_bfloat16* Ah = (__nv_bfloat16*)dynsm;            // [2][64][ROW]
    __nv_bfloat16* Al = Ah + 2 * 64 * ROW;
    __nv_bfloat16* Bh = Al + 2 * 64 * ROW;                // [2][NTILE][ROW]
    __nv_bfloat16* Bl = Bh + 2 * NTILE * ROW;

    const int t    = threadIdx.x;
    const int nb   = blockIdx.x * NTILE;
    const int koff = blockIdx.y * Kchunk;
    const int w    = t >> 5, l = t & 31;
    const int g    = l >> 2, tg = l & 3;
    const int mh   = w & 1, nq = w >> 1;
    const int grp  = l >> 3, rr = l & 7;

    // loader indices: thread covers rows lr (+32) with 4 consecutive k at lc
    const int lr = t >> 3;
    const int lc = (t & 7) * 4;

    float acc[2][NSUB][4];
    #pragma unroll
    for (int ms = 0; ms < 2; ms++)
        #pragma unroll
        for (int s = 0; s < NSUB; s++)
            #pragma unroll
            for (int i = 0; i < 4; i++) acc[ms][s][i] = 0.f;

    const uint32_t aB  = (uint32_t)__cvta_generic_to_shared(Ah);
    const uint32_t alB = (uint32_t)__cvta_generic_to_shared(Al);
    const uint32_t bB  = (uint32_t)__cvta_generic_to_shared(Bh);
    const uint32_t blB = (uint32_t)__cvta_generic_to_shared(Bl);
    const int acol = (grp >> 1) * 8;
    uint32_t aAddr[2], alAddr[2], bAddr[NPAIR], blAddr[NPAIR];
    #pragma unroll
    for (int ms = 0; ms < 2; ms++) {
        int row = mh * 32 + ms * 16 + (grp & 1) * 8 + rr;
        aAddr[ms]  = aB  + (row * ROW + acol) * 2;
        alAddr[ms] = alB + (row * ROW + acol) * 2;
    }
    #pragma unroll
    for (int p = 0; p < NPAIR; p++) {
        int row = nq * (NTILE / 4) + p * 16 + (grp & 1) * 8 + rr;
        bAddr[p]  = bB  + (row * ROW + acol) * 2;
        blAddr[p] = blB + (row * ROW + acol) * 2;
    }

    const float* Ap = A + koff;
    const float* Wp = W + koff;
    const int niter = Kchunk / 32;

    float4 pa[2], pb[BLD];
    pa[0] = *(const float4*)(Ap + (size_t)lr * K + lc);
    pa[1] = *(const float4*)(Ap + (size_t)(lr + 32) * K + lc);
    #pragma unroll
    for (int j = 0; j < BLD; j++)
        pb[j] = *(const float4*)(Wp + (size_t)(nb + lr + 32 * j) * K + lc);

    int cur = 0;
    for (int c = 0; c < niter; c++) {
        split4_store(pa[0], &Ah[(cur * 64 + lr) * ROW + lc],      &Al[(cur * 64 + lr) * ROW + lc]);
        split4_store(pa[1], &Ah[(cur * 64 + lr + 32) * ROW + lc], &Al[(cur * 64 + lr + 32) * ROW + lc]);
        #pragma unroll
        for (int j = 0; j < BLD; j++)
            split4_store(pb[j], &Bh[(cur * NTILE + lr + 32 * j) * ROW + lc],
                                &Bl[(cur * NTILE + lr + 32 * j) * ROW + lc]);
        __syncthreads();

        if (c + 1 < niter) {
            int kb = (c + 1) * 32;
            pa[0] = *(const float4*)(Ap + (size_t)lr * K + kb + lc);
            pa[1] = *(const float4*)(Ap + (size_t)(lr + 32) * K + kb + lc);
            #pragma unroll
            for (int j = 0; j < BLD; j++)
                pb[j] = *(const float4*)(Wp + (size_t)(nb + lr + 32 * j) * K + kb + lc);
        }

        const uint32_t oa = cur * ABUF, ob = cur * BBUF;
        #pragma unroll
        for (int kk = 0; kk < 32; kk += 16) {
            uint32_t ah[2][4], al_[2][4];
            #pragma unroll
            for (int ms = 0; ms < 2; ms++) {
                ldsm4(ah[ms][0], ah[ms][1], ah[ms][2], ah[ms][3], aAddr[ms] + oa + kk * 2);
                ldsm4(al_[ms][0], al_[ms][1], al_[ms][2], al_[ms][3], alAddr[ms] + oa + kk * 2);
            }
            #pragma unroll
            for (int p = 0; p < NPAIR; p++) {
                uint32_t bh[4], bl_[4];
                ldsm4(bh[0], bh[1], bh[2], bh[3], bAddr[p] + ob + kk * 2);
                ldsm4(bl_[0], bl_[1], bl_[2], bl_[3], blAddr[p] + ob + kk * 2);
                // n+0 strip: k-halves (r0, r2); n+8 strip: (r1, r3)
                #pragma unroll
                for (int ms = 0; ms < 2; ms++) {
                    mma16816(acc[ms][2 * p],     ah[ms],  bh[0],  bh[2]);
                    mma16816(acc[ms][2 * p],     ah[ms],  bl_[0], bl_[2]);
                    mma16816(acc[ms][2 * p],     al_[ms], bh[0],  bh[2]);
                    mma16816(acc[ms][2 * p + 1], ah[ms],  bh[1],  bh[3]);
                    mma16816(acc[ms][2 * p + 1], ah[ms],  bl_[1], bl_[3]);
                    mma16816(acc[ms][2 * p + 1], al_[ms], bh[1],  bh[3]);
                }
            }
        }
        cur ^= 1;
    }

    float* outp = out + (size_t)blockIdx.y * 64 * N;
    #pragma unroll
    for (int ms = 0; ms < 2; ms++) {
        #pragma unroll
        for (int s = 0; s < NSUB; s++) {
            const int r0 = mh * 32 + ms * 16 + g;
            const int r1 = r0 + 8;
            const int col = nb + nq * (NTILE / 4) + s * 8 + tg * 2;
            const int rws[4] = {r0, r0, r1, r1};
            const int cls[4] = {col, col + 1, col, col + 1};
            #pragma unroll
            for (int i = 0; i < 4; i++) {
                float o = acc[ms][s][i];
                if constexpr (EPI == EPI_SILU) {
                    float gv = aux[(size_t)rws[i] * N + cls[i]];
                    o *= gv / (1.f + expf(-gv));
                }
                outp[(size_t)rws[i] * N + cls[i]] = o;
            }
        }
    }
}

// ---------------- split-K reduce --------------------------------------------
enum { RED_NONE = 0, RED_BIAS = 1, RED_RESID = 2 };

template<int SK, int MODE>
__global__ __launch_bounds__(256) void reduce_kernel(const float* __restrict__ part,
                                                     const float* __restrict__ extra,
                                                     float* __restrict__ out,
                                                     int total, int N)
{
    int i = blockIdx.x * 256 + threadIdx.x;
    if (i >= total) return;
    float s = 0.f;
    #pragma unroll
    for (int k = 0; k < SK; k++) s += part[(size_t)k * total + i];
    if constexpr (MODE == RED_BIAS)  s += extra[i % N];
    if constexpr (MODE == RED_RESID) s += extra[i];
    out[i] = s;
}

// ---------------- RoPE (double-precision angles) ----------------------------
__global__ __launch_bounds__(256) void rope_kernel(float* __restrict__ q,
                                                   const float* __restrict__ k,
                                                   const float* __restrict__ v,
                                                   const int* __restrict__ positions,
                                                   float* __restrict__ knew,
                                                   float* __restrict__ vnew)
{
    int b = blockIdx.x, t = threadIdx.x;
    double pos = (double)positions[b];
    const double L = 13.815510557964274104107948728106; // ln(1e6)

    for (int i = t; i < NH * 64; i += 256) {
        int h = i >> 6, d = i & 63;
        double inv = exp(-(double)(2 * d) * (1.0 / HD) * L);
        double cd, sd; sincos(pos * inv, &cd, &sd);
        float c = (float)cd, s = (float)sd;
        float* base = q + b * NH * HD + h * HD + d;
        float t1 = base[0], t2 = base[64];
        base[0]  = t1 * c - t2 * s;
        base[64] = t2 * c + t1 * s;
    }
    for (int i = t; i < NKV * 64; i += 256) {
        int h = i >> 6, d = i & 63;
        double inv = exp(-(double)(2 * d) * (1.0 / HD) * L);
        double cd, sd; sincos(pos * inv, &cd, &sd);
        float c = (float)cd, s = (float)sd;
        const float* src = k + b * NKV * HD + h * HD + d;
        float t1 = src[0], t2 = src[64];
        float* dst = knew + b * NKV * HD + h * HD + d;
        dst[0]  = t1 * c - t2 * s;
        dst[64] = t2 * c + t1 * s;
    }
    for (int i = t; i < NKV * HD; i += 256)
        vnew[b * NKV * HD + i] = v[b * NKV * HD + i];
}

// ---------------- Paged attention (KV-split x2, online softmax) -------------
__global__ __launch_bounds__(256, 1) void attn_kernel(const float* __restrict__ kc,
                                                      const float* __restrict__ vc,
                                                      const int* __restrict__ block_tables,
                                                      const int* __restrict__ seq_lens,
                                                      const float* __restrict__ qbuf,
                                                      const float* __restrict__ knew,
                                                      const float* __restrict__ vnew,
                                                      float* __restrict__ partP,
                                                      float* __restrict__ partM,
                                                      float* __restrict__ partL)
{
    const int kvh = blockIdx.x, b = blockIdx.y, split = blockIdx.z;
    const int t = threadIdx.x;
    const int seq = seq_lens[b];
    const int pos = seq - 1;

    const int ntiles = (seq + 31) >> 5;
    const int half = (ntiles + 1) >> 1;
    const int t0 = split ? half : 0;
    const int t1 = split ? ntiles : half;

    extern __shared__ __align__(16) char dynsm[];
    float* q_s = (float*)dynsm;                 // [GROUP][HD]
    float* k_s = q_s + GROUP * HD;              // [2][32][132]
    float* v_s = k_s + 2 * 32 * 132;            // [2][32][132]
    __shared__ int bt_s[MAX_BLOCKS];
    __shared__ float p_s[GROUP][32];
    __shared__ float m_s[GROUP], l_s[GROUP], sc_s[GROUP];

    const uint32_t kBase = (uint32_t)__cvta_generic_to_shared(k_s);
    const uint32_t vBase = (uint32_t)__cvta_generic_to_shared(v_s);

    for (int i = t; i < MAX_BLOCKS; i += 256) bt_s[i] = block_tables[b * MAX_BLOCKS + i];
    for (int i = t; i < GROUP * HD; i += 256)
        q_s[i] = qbuf[b * NH * HD + kvh * GROUP * HD + i];
    if (t < GROUP) { m_s[t] = -1e30f; l_s[t] = 0.f; }
    __syncthreads();

    const int w = t >> 5, lane = t & 31;
    const int hh = lane >> 2, dq = lane & 3;
    const int hsel = hh < GROUP ? hh : GROUP - 1;
    const int dpv = w * 16 + dq * 4;
    float acc[4] = {0.f, 0.f, 0.f, 0.f};

    auto issue_tile = [&](int tile, int buf) {
        const int tbase = tile << 5;
        #pragma unroll
        for (int j = 0; j < 4; j++) {
            int i = t + 256 * j;
            int tt = i >> 5, d4 = (i & 31) << 2;
            int tok = tbase + tt;
            const float *ksrc, *vsrc;
            if (tok == pos) {
                int off = b * NKV * HD + kvh * HD + d4;
                ksrc = knew + off; vsrc = vnew + off;
            } else {
                int blk = bt_s[tok >> 4];
                int base = ((blk << 4) + (tok & 15)) * (NKV * HD) + kvh * HD + d4;
                ksrc = kc + base; vsrc = vc + base;
            }
            uint32_t soff = ((buf * 32 + tt) * 132 + d4) * 4;
            cp16(kBase + soff, ksrc);
            cp16(vBase + soff, vsrc);
        }
        CP_COMMIT();
    };

    issue_tile(t0, 0);
    int cur = 0;

    for (int tile = t0; tile < t1; tile++) {
        CP_WAIT_ALL();
        __syncthreads();
        if (tile + 1 < t1) issue_tile(tile + 1, cur ^ 1);

        const int tbase = tile << 5;
        const float* kb = k_s + cur * 32 * 132;
        const float* vb = v_s + cur * 32 * 132;

        if (w < GROUP) {
            float sc = 0.f;
            #pragma unroll
            for (int d4 = 0; d4 < HD; d4 += 4) {
                float4 qv = *(const float4*)&q_s[w * HD + d4];
                float4 kv = *(const float4*)&kb[lane * 132 + d4];
                sc = fmaf(qv.x, kv.x, sc); sc = fmaf(qv.y, kv.y, sc);
                sc = fmaf(qv.z, kv.z, sc); sc = fmaf(qv.w, kv.w, sc);
            }
            sc *= 0.08838834764831845f;            // HD^-0.5
            if (tbase + lane >= seq) sc = -1e30f;

            float mx = sc;
            #pragma unroll
            for (int o = 16; o; o >>= 1) mx = fmaxf(mx, __shfl_xor_sync(0xffffffffu, mx, o));
            float m_old = m_s[w];
            float m_new = fmaxf(m_old, mx);
            float p = expf(sc - m_new);
            p_s[w][lane] = p;
            float sum = p;
            #pragma unroll
            for (int o = 16; o; o >>= 1) sum += __shfl_xor_sync(0xffffffffu, sum, o);
            if (lane == 0) {
                float scl = expf(m_old - m_new);
                sc_s[w] = scl;
                l_s[w] = l_s[w] * scl + sum;
                m_s[w] = m_new;
            }
        }
        __syncthreads();

        // P.V: all 8 warps; V tile read exactly once across the CTA
        {
            float scl = sc_s[hsel];
            acc[0] *= scl; acc[1] *= scl; acc[2] *= scl; acc[3] *= scl;
            #pragma unroll 8
            for (int tt = 0; tt < 32; tt++) {
                float p = p_s[hsel][tt];
                float4 v4 = *(const float4*)&vb[tt * 132 + dpv];
                acc[0] = fmaf(p, v4.x, acc[0]);
                acc[1] = fmaf(p, v4.y, acc[1]);
                acc[2] = fmaf(p, v4.z, acc[2]);
                acc[3] = fmaf(p, v4.w, acc[3]);
            }
        }
        __syncthreads();
        cur ^= 1;
    }

    if (hh < GROUP) {
        size_t base = ((((size_t)split * BS + b) * NKV + kvh) * GROUP + hh) * HD + dpv;
        float4 o; o.x = acc[0]; o.y = acc[1]; o.z = acc[2]; o.w = acc[3];
        *(float4*)(partP + base) = o;
        if (w == 0 && dq == 0) {
            size_t mlb = (((size_t)split * BS + b) * NKV + kvh) * GROUP + hh;
            partM[mlb] = m_s[hh];
            partL[mlb] = l_s[hh];
        }
    }
}

// merge the 2 KV splits
__global__ __launch_bounds__(256) void attn_merge_kernel(const float* __restrict__ partP,
                                                         const float* __restrict__ partM,
                                                         const float* __restrict__ partL,
                                                         float* __restrict__ attn_out)
{
    const int total = BS * NKV * GROUP * HD;
    int i = blockIdx.x * 256 + threadIdx.x;
    if (i >= total) return;
    int ml = i >> 7;    // (b*NKV + kvh)*GROUP + hh
    int d  = i & 127;
    float m0 = partM[ml], m1 = partM[total / HD + ml];
    float l0 = partL[ml], l1 = partL[total / HD + ml];
    float M = fmaxf(m0, m1);
    float w0 = expf(m0 - M), w1 = expf(m1 - M);
    float denom = l0 * w0 + l1 * w1;
    float a0 = partP[i], a1 = partP[total + i];
    int b = ml / (NKV * GROUP);
    int rest = ml % (NKV * GROUP);   // kvh*GROUP + hh == head index
    attn_out[((size_t)b * NH + rest) * HD + d] = (a0 * w0 + a1 * w1) / denom;
}

// ---------------- launch ----------------------------------------------------
extern "C" void kernel_launch(void* const* d_in, const int* in_sizes, int n_in,
                              void* d_out, int out_size)
{
    const float* x            = (const float*)d_in[0];
    const int*   positions    = (const int*)  d_in[1];
    const float* k_cache      = (const float*)d_in[2];
    const float* v_cache      = (const float*)d_in[3];
    const int*   block_tables = (const int*)  d_in[4];
    const int*   seq_lens     = (const int*)  d_in[5];
    /* d_in[6] slot_mapping: unused (pos == seq_len-1 substitution instead) */
    const float* in_w   = (const float*)d_in[7];
    const float* post_w = (const float*)d_in[8];
    const float* Wq = (const float*)d_in[9];
    const float* bq = (const float*)d_in[10];
    const float* Wk = (const float*)d_in[11];
    const float* bk = (const float*)d_in[12];
    const float* Wv = (const float*)d_in[13];
    const float* bv = (const float*)d_in[14];
    const float* Wo = (const float*)d_in[15];
    const float* Wg = (const float*)d_in[16];
    const float* Wu = (const float*)d_in[17];
    const float* Wd = (const float*)d_in[18];
    float* out = (float*)d_out;

    float *p_h, *p_q, *p_k, *p_v, *p_kn, *p_vn, *p_attn, *p_hidden, *p_h2, *p_gate, *p_act;
    float *pQ, *pK, *pV, *pO, *pD, *aP, *aM, *aL;
    cudaGetSymbolAddress((void**)&p_h,      g_h);
    cudaGetSymbolAddress((void**)&p_q,      g_q);
    cudaGetSymbolAddress((void**)&p_k,      g_k);
    cudaGetSymbolAddress((void**)&p_v,      g_v);
    cudaGetSymbolAddress((void**)&p_kn,     g_knew);
    cudaGetSymbolAddress((void**)&p_vn,     g_vnew);
    cudaGetSymbolAddress((void**)&p_attn,   g_attn);
    cudaGetSymbolAddress((void**)&p_hidden, g_hidden);
    cudaGetSymbolAddress((void**)&p_h2,     g_h2);
    cudaGetSymbolAddress((void**)&p_gate,   g_gate);
    cudaGetSymbolAddress((void**)&p_act,    g_act);
    cudaGetSymbolAddress((void**)&pQ, g_pQ);
    cudaGetSymbolAddress((void**)&pK, g_pK);
    cudaGetSymbolAddress((void**)&pV, g_pV);
    cudaGetSymbolAddress((void**)&pO, g_pO);
    cudaGetSymbolAddress((void**)&pD, g_pD);
    cudaGetSymbolAddress((void**)&aP, g_attP);
    cudaGetSymbolAddress((void**)&aM, g_attM);
    cudaGetSymbolAddress((void**)&aL, g_attL);

    constexpr int SM128 = 2 * (64 + 64 + 128 + 128) * 40 * 2;   // 61440
    constexpr int SM64  = 2 * (64 + 64 + 64 + 64) * 40 * 2;     // 40960
    constexpr int SMATT = (GROUP * HD + 4 * 32 * 132) * 4;      // 71168

    cudaFuncSetAttribute(mma_gemm<128, EPI_NONE>, cudaFuncAttributeMaxDynamicSharedMemorySize, SM128);
    cudaFuncSetAttribute(mma_gemm<64,  EPI_NONE>, cudaFuncAttributeMaxDynamicSharedMemorySize, SM64);
    cudaFuncSetAttribute(mma_gemm<64,  EPI_SILU>, cudaFuncAttributeMaxDynamicSharedMemorySize, SM64);
    cudaFuncSetAttribute(attn_kernel, cudaFuncAttributeMaxDynamicSharedMemorySize, SMATT);

    rmsnorm_kernel<<<BS, 256>>>(x, in_w, p_h);

    // QKV projections (split-K 8)
    mma_gemm<128, EPI_NONE><<<dim3(NH * HD / 128, 8), 256, SM128>>>(p_h, Wq, nullptr, pQ, NH * HD, HID, HID / 8);
    mma_gemm<64,  EPI_NONE><<<dim3(NKV * HD / 64, 8), 256, SM64>>>(p_h, Wk, nullptr, pK, NKV * HD, HID, HID / 8);
    mma_gemm<64,  EPI_NONE><<<dim3(NKV * HD / 64, 8), 256, SM64>>>(p_h, Wv, nullptr, pV, NKV * HD, HID, HID / 8);
    reduce_kernel<8, RED_BIAS><<<(BS * NH * HD) / 256, 256>>>(pQ, bq, p_q, BS * NH * HD, NH * HD);
    reduce_kernel<8, RED_BIAS><<<(BS * NKV * HD) / 256, 256>>>(pK, bk, p_k, BS * NKV * HD, NKV * HD);
    reduce_kernel<8, RED_BIAS><<<(BS * NKV * HD) / 256, 256>>>(pV, bv, p_v, BS * NKV * HD, NKV * HD);

    rope_kernel<<<BS, 256>>>(p_q, p_k, p_v, positions, p_kn, p_vn);

    attn_kernel<<<dim3(NKV, BS, 2), 256, SMATT>>>(k_cache, v_cache, block_tables, seq_lens,
                                                  p_q, p_kn, p_vn, aP, aM, aL);
    attn_merge_kernel<<<(BS * NKV * GROUP * HD) / 256, 256>>>(aP, aM, aL, p_attn);

    // O projection (split-K 8) + residual
    mma_gemm<128, EPI_NONE><<<dim3(HID / 128, 8), 256, SM128>>>(p_attn, Wo, nullptr, pO, HID, NH * HD, (NH * HD) / 8);
    reduce_kernel<8, RED_RESID><<<(BS * HID) / 256, 256>>>(pO, x, p_hidden, BS * HID, HID);

    rmsnorm_kernel<<<BS, 256>>>(p_hidden, post_w, p_h2);

    // MLP: NTILE=64 (grid 296, 41 KB smem -> multiple resident CTAs/SM)
    mma_gemm<64, EPI_NONE><<<dim3(INTER / 64, 1), 256, SM64>>>(p_h2, Wg, nullptr, p_gate, INTER, HID, HID);
    mma_gemm<64, EPI_SILU><<<dim3(INTER / 64, 1), 256, SM64>>>(p_h2, Wu, p_gate, p_act, INTER, HID, HID);

    // down projection (split-K 8) + residual
    mma_gemm<128, EPI_NONE><<<dim3(HID / 128, 8), 256, SM128>>>(p_act, Wd, nullptr, pD, HID, INTER, INTER / 8);
    reduce_kernel<8, RED_RESID><<<(BS * HID) / 256, 256>>>(pD, p_hidden, out, BS * HID, HID);
}

// round 16
// speedup vs baseline: 1.6157x; 1.0591x over previous
#include <cuda_runtime.h>
#include <cuda_bf16.h>
#include <math.h>
#include <stdint.h>

#define HID   3584
#define NH    28
#define NKV   4
#define HD    128
#define INTER 18944
#define BS    64
#define BLOCK 16
#define MAX_BLOCKS 128
#define GROUP 7   // NH / NKV

// ---------------- scratch (device globals; no allocation allowed) ----------
__device__ float g_h[BS * HID];
__device__ float g_q[BS * NH * HD];
__device__ float g_k[BS * NKV * HD];
__device__ float g_v[BS * NKV * HD];
__device__ float g_knew[BS * NKV * HD];
__device__ float g_vnew[BS * NKV * HD];
__device__ float g_attn[BS * NH * HD];
__device__ float g_hidden[BS * HID];
__device__ float g_h2[BS * HID];
__device__ float g_act[BS * INTER];
__device__ float g_pQ[8 * BS * HID];
__device__ float g_pK[8 * BS * NKV * HD];
__device__ float g_pV[8 * BS * NKV * HD];
__device__ float g_pO[8 * BS * HID];
__device__ float g_pD[8 * BS * HID];
// attention partials: [split][b][kvh][group][hd]
__device__ float g_attP[2 * BS * NKV * GROUP * HD];
__device__ float g_attM[2 * BS * NKV * GROUP];
__device__ float g_attL[2 * BS * NKV * GROUP];

// ---------------- helpers ---------------------------------------------------
__device__ __forceinline__ void ldsm4(uint32_t& r0, uint32_t& r1, uint32_t& r2, uint32_t& r3,
                                      uint32_t addr)
{
    asm volatile("ldmatrix.sync.aligned.m8n8.x4.shared.b16 {%0,%1,%2,%3}, [%4];"
                 : "=r"(r0), "=r"(r1), "=r"(r2), "=r"(r3) : "r"(addr));
}

__device__ __forceinline__ void mma16816(float* c, const uint32_t* a, uint32_t b0, uint32_t b1)
{
    asm volatile("mma.sync.aligned.m16n8k16.row.col.f32.bf16.bf16.f32 "
                 "{%0,%1,%2,%3}, {%4,%5,%6,%7}, {%8,%9}, {%0,%1,%2,%3};"
                 : "+f"(c[0]), "+f"(c[1]), "+f"(c[2]), "+f"(c[3])
                 : "r"(a[0]), "r"(a[1]), "r"(a[2]), "r"(a[3]), "r"(b0), "r"(b1));
}

__device__ __forceinline__ uint32_t packbf2(__nv_bfloat16 a, __nv_bfloat16 b)
{
    __nv_bfloat162 t = __halves2bfloat162(a, b);
    uint32_t u; memcpy(&u, &t, 4); return u;
}

// split a float4 into hi/lo bf16 quads, store as 8B each
__device__ __forceinline__ void split4_store(float4 v, __nv_bfloat16* hp, __nv_bfloat16* lp)
{
    __nv_bfloat16 h0 = __float2bfloat16_rn(v.x), h1 = __float2bfloat16_rn(v.y);
    __nv_bfloat16 h2 = __float2bfloat16_rn(v.z), h3 = __float2bfloat16_rn(v.w);
    __nv_bfloat16 l0 = __float2bfloat16_rn(v.x - __bfloat162float(h0));
    __nv_bfloat16 l1 = __float2bfloat16_rn(v.y - __bfloat162float(h1));
    __nv_bfloat16 l2 = __float2bfloat16_rn(v.z - __bfloat162float(h2));
    __nv_bfloat16 l3 = __float2bfloat16_rn(v.w - __bfloat162float(h3));
    uint2 hu; hu.x = packbf2(h0, h1); hu.y = packbf2(h2, h3);
    uint2 lu; lu.x = packbf2(l0, l1); lu.y = packbf2(l2, l3);
    *(uint2*)hp = hu;
    *(uint2*)lp = lu;
}

__device__ __forceinline__ void cp16(uint32_t dst, const void* src)
{
    asm volatile("cp.async.cg.shared.global [%0], [%1], 16;" :: "r"(dst), "l"(src));
}
#define CP_COMMIT() asm volatile("cp.async.commit_group;")
#define CP_WAIT_ALL() asm volatile("cp.async.wait_group 0;")

// ---------------- RMSNorm ---------------------------------------------------
__global__ __launch_bounds__(256) void rmsnorm_kernel(const float* __restrict__ x,
                                                      const float* __restrict__ w,
                                                      float* __restrict__ out)
{
    int b = blockIdx.x, t = threadIdx.x;
    const float4* x4 = (const float4*)(x + b * HID);
    const float4* w4 = (const float4*)w;
    float4* o4 = (float4*)(out + b * HID);

    float ss = 0.f;
    for (int i = t; i < HID / 4; i += 256) {
        float4 v = x4[i];
        ss += v.x * v.x + v.y * v.y + v.z * v.z + v.w * v.w;
    }
    #pragma unroll
    for (int o = 16; o; o >>= 1) ss += __shfl_xor_sync(0xffffffffu, ss, o);

    __shared__ float red[8];
    __shared__ float s_rs;
    if ((t & 31) == 0) red[t >> 5] = ss;
    __syncthreads();
    if (t == 0) {
        float tot = 0.f;
        for (int i = 0; i < 8; i++) tot += red[i];
        s_rs = rsqrtf(tot / (float)HID + 1e-6f);
    }
    __syncthreads();
    float rs = s_rs;
    for (int i = t; i < HID / 4; i += 256) {
        float4 v = x4[i], ww = w4[i];
        float4 o;
        o.x = v.x * rs * ww.x; o.y = v.y * rs * ww.y;
        o.z = v.z * rs * ww.z; o.w = v.w * rs * ww.w;
        o4[i] = o;
    }
}

// ---------------- split-bf16 3-pass ldmatrix MMA GEMM (NTILE=64, verified) --
__global__ __launch_bounds__(256, 1) void mma_gemm64(const float* __restrict__ A,
                                                     const float* __restrict__ W,
                                                     float* __restrict__ out,
                                                     int N, int K, int Kchunk)
{
    constexpr int ROW  = 40;
    constexpr int ABUF = 64 * ROW * 2;

    extern __shared__ __align__(16) char dynsm[];
    __nv_bfloat16* Ah = (__nv_bfloat16*)dynsm;            // [2][64][ROW]
    __nv_bfloat16* Al = Ah + 2 * 64 * ROW;
    __nv_bfloat16* Bh = Al + 2 * 64 * ROW;                // [2][64][ROW]
    __nv_bfloat16* Bl = Bh + 2 * 64 * ROW;

    const int t    = threadIdx.x;
    const int nb   = blockIdx.x * 64;
    const int koff = blockIdx.y * Kchunk;
    const int w    = t >> 5, l = t & 31;
    const int g    = l >> 2, tg = l & 3;
    const int mh   = w & 1, nq = w >> 1;
    const int grp  = l >> 3, rr = l & 7;

    const int lr = t >> 3;
    const int lc = (t & 7) * 4;

    float acc[2][2][4];
    #pragma unroll
    for (int ms = 0; ms < 2; ms++)
        #pragma unroll
        for (int s = 0; s < 2; s++)
            #pragma unroll
            for (int i = 0; i < 4; i++) acc[ms][s][i] = 0.f;

    const uint32_t aB  = (uint32_t)__cvta_generic_to_shared(Ah);
    const uint32_t alB = (uint32_t)__cvta_generic_to_shared(Al);
    const uint32_t bB  = (uint32_t)__cvta_generic_to_shared(Bh);
    const uint32_t blB = (uint32_t)__cvta_generic_to_shared(Bl);
    const int acol = (grp >> 1) * 8;
    uint32_t aAddr[2], alAddr[2], bAddr, blAddr;
    #pragma unroll
    for (int ms = 0; ms < 2; ms++) {
        int row = mh * 32 + ms * 16 + (grp & 1) * 8 + rr;
        aAddr[ms]  = aB  + (row * ROW + acol) * 2;
        alAddr[ms] = alB + (row * ROW + acol) * 2;
    }
    {
        int row = nq * 16 + (grp & 1) * 8 + rr;
        bAddr  = bB  + (row * ROW + acol) * 2;
        blAddr = blB + (row * ROW + acol) * 2;
    }

    const float* Ap = A + koff;
    const float* Wp = W + koff;
    const int niter = Kchunk / 32;

    float4 pa[2], pb[2];
    pa[0] = *(const float4*)(Ap + (size_t)lr * K + lc);
    pa[1] = *(const float4*)(Ap + (size_t)(lr + 32) * K + lc);
    pb[0] = *(const float4*)(Wp + (size_t)(nb + lr) * K + lc);
    pb[1] = *(const float4*)(Wp + (size_t)(nb + lr + 32) * K + lc);

    int cur = 0;
    for (int c = 0; c < niter; c++) {
        split4_store(pa[0], &Ah[(cur * 64 + lr) * ROW + lc],      &Al[(cur * 64 + lr) * ROW + lc]);
        split4_store(pa[1], &Ah[(cur * 64 + lr + 32) * ROW + lc], &Al[(cur * 64 + lr + 32) * ROW + lc]);
        split4_store(pb[0], &Bh[(cur * 64 + lr) * ROW + lc],      &Bl[(cur * 64 + lr) * ROW + lc]);
        split4_store(pb[1], &Bh[(cur * 64 + lr + 32) * ROW + lc], &Bl[(cur * 64 + lr + 32) * ROW + lc]);
        __syncthreads();

        if (c + 1 < niter) {
            int kb = (c + 1) * 32;
            pa[0] = *(const float4*)(Ap + (size_t)lr * K + kb + lc);
            pa[1] = *(const float4*)(Ap + (size_t)(lr + 32) * K + kb + lc);
            pb[0] = *(const float4*)(Wp + (size_t)(nb + lr) * K + kb + lc);
            pb[1] = *(const float4*)(Wp + (size_t)(nb + lr + 32) * K + kb + lc);
        }

        const uint32_t oa = cur * ABUF, ob = cur * ABUF;
        #pragma unroll
        for (int kk = 0; kk < 32; kk += 16) {
            uint32_t ah[2][4], al_[2][4];
            #pragma unroll
            for (int ms = 0; ms < 2; ms++) {
                ldsm4(ah[ms][0], ah[ms][1], ah[ms][2], ah[ms][3], aAddr[ms] + oa + kk * 2);
                ldsm4(al_[ms][0], al_[ms][1], al_[ms][2], al_[ms][3], alAddr[ms] + oa + kk * 2);
            }
            uint32_t bh[4], bl_[4];
            ldsm4(bh[0], bh[1], bh[2], bh[3], bAddr + ob + kk * 2);
            ldsm4(bl_[0], bl_[1], bl_[2], bl_[3], blAddr + ob + kk * 2);
            #pragma unroll
            for (int ms = 0; ms < 2; ms++) {
                mma16816(acc[ms][0], ah[ms],  bh[0],  bh[2]);
                mma16816(acc[ms][0], ah[ms],  bl_[0], bl_[2]);
                mma16816(acc[ms][0], al_[ms], bh[0],  bh[2]);
                mma16816(acc[ms][1], ah[ms],  bh[1],  bh[3]);
                mma16816(acc[ms][1], ah[ms],  bl_[1], bl_[3]);
                mma16816(acc[ms][1], al_[ms], bh[1],  bh[3]);
            }
        }
        cur ^= 1;
    }

    float* outp = out + (size_t)blockIdx.y * 64 * N;
    #pragma unroll
    for (int ms = 0; ms < 2; ms++) {
        #pragma unroll
        for (int s = 0; s < 2; s++) {
            const int r0 = mh * 32 + ms * 16 + g;
            const int r1 = r0 + 8;
            const int col = nb + nq * 16 + s * 8 + tg * 2;
            outp[(size_t)r0 * N + col]     = acc[ms][s][0];
            outp[(size_t)r0 * N + col + 1] = acc[ms][s][1];
            outp[(size_t)r1 * N + col]     = acc[ms][s][2];
            outp[(size_t)r1 * N + col + 1] = acc[ms][s][3];
        }
    }
}

// ---------------- fused gate+up MLP GEMM (NTILE=64 each, shared A frags) ----
// act[64, nb:nb+64] = silu(A @ Wg^T) * (A @ Wu^T)
__global__ __launch_bounds__(256, 1) void mlp_gateup_kernel(const float* __restrict__ A,
                                                            const float* __restrict__ Wg,
                                                            const float* __restrict__ Wu,
                                                            float* __restrict__ act,
                                                            int N, int K)
{
    constexpr int ROW  = 40;
    constexpr int ABUF = 64 * ROW * 2;

    extern __shared__ __align__(16) char dynsm[];
    __nv_bfloat16* Ah  = (__nv_bfloat16*)dynsm;           // [2][64][ROW] each
    __nv_bfloat16* Al  = Ah  + 2 * 64 * ROW;
    __nv_bfloat16* Bgh = Al  + 2 * 64 * ROW;
    __nv_bfloat16* Bgl = Bgh + 2 * 64 * ROW;
    __nv_bfloat16* Buh = Bgl + 2 * 64 * ROW;
    __nv_bfloat16* Bul = Buh + 2 * 64 * ROW;

    const int t  = threadIdx.x;
    const int nb = blockIdx.x * 64;
    const int w  = t >> 5, l = t & 31;
    const int g  = l >> 2, tg = l & 3;
    const int mh = w & 1, nq = w >> 1;
    const int grp = l >> 3, rr = l & 7;

    const int lr = t >> 3;
    const int lc = (t & 7) * 4;

    float accg[2][2][4], accu[2][2][4];
    #pragma unroll
    for (int ms = 0; ms < 2; ms++)
        #pragma unroll
        for (int s = 0; s < 2; s++)
            #pragma unroll
            for (int i = 0; i < 4; i++) { accg[ms][s][i] = 0.f; accu[ms][s][i] = 0.f; }

    const uint32_t aB   = (uint32_t)__cvta_generic_to_shared(Ah);
    const uint32_t alB  = (uint32_t)__cvta_generic_to_shared(Al);
    const uint32_t bgB  = (uint32_t)__cvta_generic_to_shared(Bgh);
    const uint32_t bglB = (uint32_t)__cvta_generic_to_shared(Bgl);
    const uint32_t buB  = (uint32_t)__cvta_generic_to_shared(Buh);
    const uint32_t bulB = (uint32_t)__cvta_generic_to_shared(Bul);
    const int acol = (grp >> 1) * 8;
    uint32_t aAddr[2], alAddr[2], bgA, bglA, buA, bulA;
    #pragma unroll
    for (int ms = 0; ms < 2; ms++) {
        int row = mh * 32 + ms * 16 + (grp & 1) * 8 + rr;
        aAddr[ms]  = aB  + (row * ROW + acol) * 2;
        alAddr[ms] = alB + (row * ROW + acol) * 2;
    }
    {
        int row = nq * 16 + (grp & 1) * 8 + rr;
        bgA  = bgB  + (row * ROW + acol) * 2;
        bglA = bglB + (row * ROW + acol) * 2;
        buA  = buB  + (row * ROW + acol) * 2;
        bulA = bulB + (row * ROW + acol) * 2;
    }

    const int niter = K / 32;

    float4 pa[2], pg[2], pu[2];
    pa[0] = *(const float4*)(A + (size_t)lr * K + lc);
    pa[1] = *(const float4*)(A + (size_t)(lr + 32) * K + lc);
    pg[0] = *(const float4*)(Wg + (size_t)(nb + lr) * K + lc);
    pg[1] = *(const float4*)(Wg + (size_t)(nb + lr + 32) * K + lc);
    pu[0] = *(const float4*)(Wu + (size_t)(nb + lr) * K + lc);
    pu[1] = *(const float4*)(Wu + (size_t)(nb + lr + 32) * K + lc);

    int cur = 0;
    for (int c = 0; c < niter; c++) {
        split4_store(pa[0], &Ah[(cur * 64 + lr) * ROW + lc],       &Al[(cur * 64 + lr) * ROW + lc]);
        split4_store(pa[1], &Ah[(cur * 64 + lr + 32) * ROW + lc],  &Al[(cur * 64 + lr + 32) * ROW + lc]);
        split4_store(pg[0], &Bgh[(cur * 64 + lr) * ROW + lc],      &Bgl[(cur * 64 + lr) * ROW + lc]);
        split4_store(pg[1], &Bgh[(cur * 64 + lr + 32) * ROW + lc], &Bgl[(cur * 64 + lr + 32) * ROW + lc]);
        split4_store(pu[0], &Buh[(cur * 64 + lr) * ROW + lc],      &Bul[(cur * 64 + lr) * ROW + lc]);
        split4_store(pu[1], &Buh[(cur * 64 + lr + 32) * ROW + lc], &Bul[(cur * 64 + lr + 32) * ROW + lc]);
        __syncthreads();

        if (c + 1 < niter) {
            int kb = (c + 1) * 32;
            pa[0] = *(const float4*)(A + (size_t)lr * K + kb + lc);
            pa[1] = *(const float4*)(A + (size_t)(lr + 32) * K + kb + lc);
            pg[0] = *(const float4*)(Wg + (size_t)(nb + lr) * K + kb + lc);
            pg[1] = *(const float4*)(Wg + (size_t)(nb + lr + 32) * K + kb + lc);
            pu[0] = *(const float4*)(Wu + (size_t)(nb + lr) * K + kb + lc);
            pu[1] = *(const float4*)(Wu + (size_t)(nb + lr + 32) * K + kb + lc);
        }

        const uint32_t off = cur * ABUF;
        #pragma unroll
        for (int kk = 0; kk < 32; kk += 16) {
            uint32_t ah[2][4], al_[2][4];
            #pragma unroll
            for (int ms = 0; ms < 2; ms++) {
                ldsm4(ah[ms][0], ah[ms][1], ah[ms][2], ah[ms][3], aAddr[ms] + off + kk * 2);
                ldsm4(al_[ms][0], al_[ms][1], al_[ms][2], al_[ms][3], alAddr[ms] + off + kk * 2);
            }
            uint32_t gh[4], gl[4], uh[4], ul[4];
            ldsm4(gh[0], gh[1], gh[2], gh[3], bgA  + off + kk * 2);
            ldsm4(gl[0], gl[1], gl[2], gl[3], bglA + off + kk * 2);
            ldsm4(uh[0], uh[1], uh[2], uh[3], buA  + off + kk * 2);
            ldsm4(ul[0], ul[1], ul[2], ul[3], bulA + off + kk * 2);
            #pragma unroll
            for (int ms = 0; ms < 2; ms++) {
                mma16816(accg[ms][0], ah[ms],  gh[0], gh[2]);
                mma16816(accg[ms][0], ah[ms],  gl[0], gl[2]);
                mma16816(accg[ms][0], al_[ms], gh[0], gh[2]);
                mma16816(accg[ms][1], ah[ms],  gh[1], gh[3]);
                mma16816(accg[ms][1], ah[ms],  gl[1], gl[3]);
                mma16816(accg[ms][1], al_[ms], gh[1], gh[3]);
                mma16816(accu[ms][0], ah[ms],  uh[0], uh[2]);
                mma16816(accu[ms][0], ah[ms],  ul[0], ul[2]);
                mma16816(accu[ms][0], al_[ms], uh[0], uh[2]);
                mma16816(accu[ms][1], ah[ms],  uh[1], uh[3]);
                mma16816(accu[ms][1], ah[ms],  ul[1], ul[3]);
                mma16816(accu[ms][1], al_[ms], uh[1], uh[3]);
            }
        }
        cur ^= 1;
    }

    #pragma unroll
    for (int ms = 0; ms < 2; ms++) {
        #pragma unroll
        for (int s = 0; s < 2; s++) {
            const int r0 = mh * 32 + ms * 16 + g;
            const int r1 = r0 + 8;
            const int col = nb + nq * 16 + s * 8 + tg * 2;
            const int rws[4] = {r0, r0, r1, r1};
            const int cls[4] = {col, col + 1, col, col + 1};
            #pragma unroll
            for (int i = 0; i < 4; i++) {
                float gv = accg[ms][s][i];
                float uv = accu[ms][s][i];
                act[(size_t)rws[i] * N + cls[i]] = uv * (gv / (1.f + expf(-gv)));
            }
        }
    }
}

// ---------------- split-K reduce --------------------------------------------
enum { RED_BIAS = 1, RED_RESID = 2 };

template<int SK, int MODE>
__global__ __launch_bounds__(256) void reduce_kernel(const float* __restrict__ part,
                                                     const float* __restrict__ extra,
                                                     float* __restrict__ out,
                                                     int total, int N)
{
    int i = blockIdx.x * 256 + threadIdx.x;
    if (i >= total) return;
    float s = 0.f;
    #pragma unroll
    for (int k = 0; k < SK; k++) s += part[(size_t)k * total + i];
    if constexpr (MODE == RED_BIAS)  s += extra[i % N];
    if constexpr (MODE == RED_RESID) s += extra[i];
    out[i] = s;
}

// ---------------- RoPE (double-precision angles) ----------------------------
__global__ __launch_bounds__(256) void rope_kernel(float* __restrict__ q,
                                                   const float* __restrict__ k,
                                                   const float* __restrict__ v,
                                                   const int* __restrict__ positions,
                                                   float* __restrict__ knew,
                                                   float* __restrict__ vnew)
{
    int b = blockIdx.x, t = threadIdx.x;
    double pos = (double)positions[b];
    const double L = 13.815510557964274104107948728106; // ln(1e6)

    for (int i = t; i < NH * 64; i += 256) {
        int h = i >> 6, d = i & 63;
        double inv = exp(-(double)(2 * d) * (1.0 / HD) * L);
        double cd, sd; sincos(pos * inv, &cd, &sd);
        float c = (float)cd, s = (float)sd;
        float* base = q + b * NH * HD + h * HD + d;
        float t1 = base[0], t2 = base[64];
        base[0]  = t1 * c - t2 * s;
        base[64] = t2 * c + t1 * s;
    }
    for (int i = t; i < NKV * 64; i += 256) {
        int h = i >> 6, d = i & 63;
        double inv = exp(-(double)(2 * d) * (1.0 / HD) * L);
        double cd, sd; sincos(pos * inv, &cd, &sd);
        float c = (float)cd, s = (float)sd;
        const float* src = k + b * NKV * HD + h * HD + d;
        float t1 = src[0], t2 = src[64];
        float* dst = knew + b * NKV * HD + h * HD + d;
        dst[0]  = t1 * c - t2 * s;
        dst[64] = t2 * c + t1 * s;
    }
    for (int i = t; i < NKV * HD; i += 256)
        vnew[b * NKV * HD + i] = v[b * NKV * HD + i];
}

// ---------------- Paged attention (KV-split x2, online softmax) -------------
__global__ __launch_bounds__(256, 1) void attn_kernel(const float* __restrict__ kc,
                                                      const float* __restrict__ vc,
                                                      const int* __restrict__ block_tables,
                                                      const int* __restrict__ seq_lens,
                                                      const float* __restrict__ qbuf,
                                                      const float* __restrict__ knew,
                                                      const float* __restrict__ vnew,
                                                      float* __restrict__ partP,
                                                      float* __restrict__ partM,
                                                      float* __restrict__ partL)
{
    const int kvh = blockIdx.x, b = blockIdx.y, split = blockIdx.z;
    const int t = threadIdx.x;
    const int seq = seq_lens[b];
    const int pos = seq - 1;

    const int ntiles = (seq + 31) >> 5;
    const int half = (ntiles + 1) >> 1;
    const int t0 = split ? half : 0;
    const int t1 = split ? ntiles : half;

    extern __shared__ __align__(16) char dynsm[];
    float* q_s = (float*)dynsm;                 // [GROUP][HD]
    float* k_s = q_s + GROUP * HD;              // [2][32][132]
    float* v_s = k_s + 2 * 32 * 132;            // [2][32][132]
    __shared__ int bt_s[MAX_BLOCKS];
    __shared__ float p_s[GROUP][32];
    __shared__ float m_s[GROUP], l_s[GROUP], sc_s[GROUP];

    const uint32_t kBase = (uint32_t)__cvta_generic_to_shared(k_s);
    const uint32_t vBase = (uint32_t)__cvta_generic_to_shared(v_s);

    for (int i = t; i < MAX_BLOCKS; i += 256) bt_s[i] = block_tables[b * MAX_BLOCKS + i];
    for (int i = t; i < GROUP * HD; i += 256)
        q_s[i] = qbuf[b * NH * HD + kvh * GROUP * HD + i];
    if (t < GROUP) { m_s[t] = -1e30f; l_s[t] = 0.f; }
    __syncthreads();

    const int w = t >> 5, lane = t & 31;
    const int hh = lane >> 2, dq = lane & 3;
    const int hsel = hh < GROUP ? hh : GROUP - 1;
    const int dpv = w * 16 + dq * 4;
    float acc[4] = {0.f, 0.f, 0.f, 0.f};

    auto issue_tile = [&](int tile, int buf) {
        const int tbase = tile << 5;
        #pragma unroll
        for (int j = 0; j < 4; j++) {
            int i = t + 256 * j;
            int tt = i >> 5, d4 = (i & 31) << 2;
            int tok = tbase + tt;
            const float *ksrc, *vsrc;
            if (tok == pos) {
                int off = b * NKV * HD + kvh * HD + d4;
                ksrc = knew + off; vsrc = vnew + off;
            } else {
                int blk = bt_s[tok >> 4];
                int base = ((blk << 4) + (tok & 15)) * (NKV * HD) + kvh * HD + d4;
                ksrc = kc + base; vsrc = vc + base;
            }
            uint32_t soff = ((buf * 32 + tt) * 132 + d4) * 4;
            cp16(kBase + soff, ksrc);
            cp16(vBase + soff, vsrc);
        }
        CP_COMMIT();
    };

    issue_tile(t0, 0);
    int cur = 0;

    for (int tile = t0; tile < t1; tile++) {
        CP_WAIT_ALL();
        __syncthreads();
        if (tile + 1 < t1) issue_tile(tile + 1, cur ^ 1);

        const int tbase = tile << 5;
        const float* kb = k_s + cur * 32 * 132;
        const float* vb = v_s + cur * 32 * 132;

        if (w < GROUP) {
            float sc = 0.f;
            #pragma unroll
            for (int d4 = 0; d4 < HD; d4 += 4) {
                float4 qv = *(const float4*)&q_s[w * HD + d4];
                float4 kv = *(const float4*)&kb[lane * 132 + d4];
                sc = fmaf(qv.x, kv.x, sc); sc = fmaf(qv.y, kv.y, sc);
                sc = fmaf(qv.z, kv.z, sc); sc = fmaf(qv.w, kv.w, sc);
            }
            sc *= 0.08838834764831845f;            // HD^-0.5
            if (tbase + lane >= seq) sc = -1e30f;

            float mx = sc;
            #pragma unroll
            for (int o = 16; o; o >>= 1) mx = fmaxf(mx, __shfl_xor_sync(0xffffffffu, mx, o));
            float m_old = m_s[w];
            float m_new = fmaxf(m_old, mx);
            float p = expf(sc - m_new);
            p_s[w][lane] = p;
            float sum = p;
            #pragma unroll
            for (int o = 16; o; o >>= 1) sum += __shfl_xor_sync(0xffffffffu, sum, o);
            if (lane == 0) {
                float scl = expf(m_old - m_new);
                sc_s[w] = scl;
                l_s[w] = l_s[w] * scl + sum;
                m_s[w] = m_new;
            }
        }
        __syncthreads();

        // P.V: all 8 warps; V tile read exactly once across the CTA
        {
            float scl = sc_s[hsel];
            acc[0] *= scl; acc[1] *= scl; acc[2] *= scl; acc[3] *= scl;
            #pragma unroll 8
            for (int tt = 0; tt < 32; tt++) {
                float p = p_s[hsel][tt];
                float4 v4 = *(const float4*)&vb[tt * 132 + dpv];
                acc[0] = fmaf(p, v4.x, acc[0]);
                acc[1] = fmaf(p, v4.y, acc[1]);
                acc[2] = fmaf(p, v4.z, acc[2]);
                acc[3] = fmaf(p, v4.w, acc[3]);
            }
        }
        __syncthreads();
        cur ^= 1;
    }

    if (hh < GROUP) {
        size_t base = ((((size_t)split * BS + b) * NKV + kvh) * GROUP + hh) * HD + dpv;
        float4 o; o.x = acc[0]; o.y = acc[1]; o.z = acc[2]; o.w = acc[3];
        *(float4*)(partP + base) = o;
        if (w == 0 && dq == 0) {
            size_t mlb = (((size_t)split * BS + b) * NKV + kvh) * GROUP + hh;
            partM[mlb] = m_s[hh];
            partL[mlb] = l_s[hh];
        }
    }
}

// merge the 2 KV splits
__global__ __launch_bounds__(256) void attn_merge_kernel(const float* __restrict__ partP,
                                                         const float* __restrict__ partM,
                                                         const float* __restrict__ partL,
                                                         float* __restrict__ attn_out)
{
    const int total = BS * NKV * GROUP * HD;
    int i = blockIdx.x * 256 + threadIdx.x;
    if (i >= total) return;
    int ml = i >> 7;    // (b*NKV + kvh)*GROUP + hh
    int d  = i & 127;
    float m0 = partM[ml], m1 = partM[total / HD + ml];
    float l0 = partL[ml], l1 = partL[total / HD + ml];
    float M = fmaxf(m0, m1);
    float w0 = expf(m0 - M), w1 = expf(m1 - M);
    float denom = l0 * w0 + l1 * w1;
    float a0 = partP[i], a1 = partP[total + i];
    int b = ml / (NKV * GROUP);
    int rest = ml % (NKV * GROUP);   // kvh*GROUP + hh == head index
    attn_out[((size_t)b * NH + rest) * HD + d] = (a0 * w0 + a1 * w1) / denom;
}

// ---------------- launch ----------------------------------------------------
extern "C" void kernel_launch(void* const* d_in, const int* in_sizes, int n_in,
                              void* d_out, int out_size)
{
    const float* x            = (const float*)d_in[0];
    const int*   positions    = (const int*)  d_in[1];
    const float* k_cache      = (const float*)d_in[2];
    const float* v_cache      = (const float*)d_in[3];
    const int*   block_tables = (const int*)  d_in[4];
    const int*   seq_lens     = (const int*)  d_in[5];
    /* d_in[6] slot_mapping: unused (pos == seq_len-1 substitution instead) */
    const float* in_w   = (const float*)d_in[7];
    const float* post_w = (const float*)d_in[8];
    const float* Wq = (const float*)d_in[9];
    const float* bq = (const float*)d_in[10];
    const float* Wk = (const float*)d_in[11];
    const float* bk = (const float*)d_in[12];
    const float* Wv = (const float*)d_in[13];
    const float* bv = (const float*)d_in[14];
    const float* Wo = (const float*)d_in[15];
    const float* Wg = (const float*)d_in[16];
    const float* Wu = (const float*)d_in[17];
    const float* Wd = (const float*)d_in[18];
    float* out = (float*)d_out;

    float *p_h, *p_q, *p_k, *p_v, *p_kn, *p_vn, *p_attn, *p_hidden, *p_h2, *p_act;
    float *pQ, *pK, *pV, *pO, *pD, *aP, *aM, *aL;
    cudaGetSymbolAddress((void**)&p_h,      g_h);
    cudaGetSymbolAddress((void**)&p_q,      g_q);
    cudaGetSymbolAddress((void**)&p_k,      g_k);
    cudaGetSymbolAddress((void**)&p_v,      g_v);
    cudaGetSymbolAddress((void**)&p_kn,     g_knew);
    cudaGetSymbolAddress((void**)&p_vn,     g_vnew);
    cudaGetSymbolAddress((void**)&p_attn,   g_attn);
    cudaGetSymbolAddress((void**)&p_hidden, g_hidden);
    cudaGetSymbolAddress((void**)&p_h2,     g_h2);
    cudaGetSymbolAddress((void**)&p_act,    g_act);
    cudaGetSymbolAddress((void**)&pQ, g_pQ);
    cudaGetSymbolAddress((void**)&pK, g_pK);
    cudaGetSymbolAddress((void**)&pV, g_pV);
    cudaGetSymbolAddress((void**)&pO, g_pO);
    cudaGetSymbolAddress((void**)&pD, g_pD);
    cudaGetSymbolAddress((void**)&aP, g_attP);
    cudaGetSymbolAddress((void**)&aM, g_attM);
    cudaGetSymbolAddress((void**)&aL, g_attL);

    constexpr int SM64  = 2 * (64 + 64 + 64 + 64) * 40 * 2;             // 40960
    constexpr int SMGU  = 2 * (64 + 64 + 64 + 64 + 64 + 64) * 40 * 2;   // 61440
    constexpr int SMATT = (GROUP * HD + 4 * 32 * 132) * 4;              // 71168

    cudaFuncSetAttribute(mma_gemm64,        cudaFuncAttributeMaxDynamicSharedMemorySize, SM64);
    cudaFuncSetAttribute(mlp_gateup_kernel, cudaFuncAttributeMaxDynamicSharedMemorySize, SMGU);
    cudaFuncSetAttribute(attn_kernel,       cudaFuncAttributeMaxDynamicSharedMemorySize, SMATT);

    rmsnorm_kernel<<<BS, 256>>>(x, in_w, p_h);

    // QKV projections (NTILE=64, split-K 8)
    mma_gemm64<<<dim3(NH * HD / 64, 8), 256, SM64>>>(p_h, Wq, pQ, NH * HD, HID, HID / 8);
    mma_gemm64<<<dim3(NKV * HD / 64, 8), 256, SM64>>>(p_h, Wk, pK, NKV * HD, HID, HID / 8);
    mma_gemm64<<<dim3(NKV * HD / 64, 8), 256, SM64>>>(p_h, Wv, pV, NKV * HD, HID, HID / 8);
    reduce_kernel<8, RED_BIAS><<<(BS * NH * HD) / 256, 256>>>(pQ, bq, p_q, BS * NH * HD, NH * HD);
    reduce_kernel<8, RED_BIAS><<<(BS * NKV * HD) / 256, 256>>>(pK, bk, p_k, BS * NKV * HD, NKV * HD);
    reduce_kernel<8, RED_BIAS><<<(BS * NKV * HD) / 256, 256>>>(pV, bv, p_v, BS * NKV * HD, NKV * HD);

    rope_kernel<<<BS, 256>>>(p_q, p_k, p_v, positions, p_kn, p_vn);

    attn_kernel<<<dim3(NKV, BS, 2), 256, SMATT>>>(k_cache, v_cache, block_tables, seq_lens,
                                                  p_q, p_kn, p_vn, aP, aM, aL);
    attn_merge_kernel<<<(BS * NKV * GROUP * HD) / 256, 256>>>(aP, aM, aL, p_attn);

    // O projection (NTILE=64, split-K 8) + residual
    mma_gemm64<<<dim3(HID / 64, 8), 256, SM64>>>(p_attn, Wo, pO, HID, NH * HD, (NH * HD) / 8);
    reduce_kernel<8, RED_RESID><<<(BS * HID) / 256, 256>>>(pO, x, p_hidden, BS * HID, HID);

    rmsnorm_kernel<<<BS, 256>>>(p_hidden, post_w, p_h2);

    // fused gate+up MLP (grid 296; shared A fragments; silu in-register)
    mlp_gateup_kernel<<<INTER / 64, 256, SMGU>>>(p_h2, Wg, Wu, p_act, INTER, HID);

    // down projection (NTILE=64, split-K 8) + residual
    mma_gemm64<<<dim3(HID / 64, 8), 256, SM64>>>(p_act, Wd, pD, HID, INTER, INTER / 8);
    reduce_kernel<8, RED_RESID><<<(BS * HID) / 256, 256>>>(pD, p_hidden, out, BS * HID, HID);
}

// round 17
// speedup vs baseline: 1.7384x; 1.0760x over previous
#include <cuda_runtime.h>
#include <cuda_bf16.h>
#include <math.h>
#include <stdint.h>

#define HID   3584
#define NH    28
#define NKV   4
#define HD    128
#define INTER 18944
#define BS    64
#define BLOCK 16
#define MAX_BLOCKS 128
#define GROUP 7   // NH / NKV
#define QKVN  ((NH + 2 * NKV) * HD)   // 4608
#define NSPL  4                        // attention KV splits

// ---------------- scratch (device globals; no allocation allowed) ----------
__device__ float g_h[BS * HID];
__device__ float g_q[BS * NH * HD];
__device__ float g_k[BS * NKV * HD];
__device__ float g_v[BS * NKV * HD];
__device__ float g_knew[BS * NKV * HD];
__device__ float g_vnew[BS * NKV * HD];
__device__ float g_attn[BS * NH * HD];
__device__ float g_hidden[BS * HID];
__device__ float g_h2[BS * HID];
__device__ float g_act[BS * INTER];
__device__ float g_pQKV[8 * BS * QKVN];
__device__ float g_pO[8 * BS * HID];
__device__ float g_pD[8 * BS * HID];
// attention partials: [split][b][kvh][group][hd]
__device__ float g_attP[NSPL * BS * NKV * GROUP * HD];
__device__ float g_attM[NSPL * BS * NKV * GROUP];
__device__ float g_attL[NSPL * BS * NKV * GROUP];

// ---------------- helpers ---------------------------------------------------
__device__ __forceinline__ void ldsm4(uint32_t& r0, uint32_t& r1, uint32_t& r2, uint32_t& r3,
                                      uint32_t addr)
{
    asm volatile("ldmatrix.sync.aligned.m8n8.x4.shared.b16 {%0,%1,%2,%3}, [%4];"
                 : "=r"(r0), "=r"(r1), "=r"(r2), "=r"(r3) : "r"(addr));
}

__device__ __forceinline__ void mma16816(float* c, const uint32_t* a, uint32_t b0, uint32_t b1)
{
    asm volatile("mma.sync.aligned.m16n8k16.row.col.f32.bf16.bf16.f32 "
                 "{%0,%1,%2,%3}, {%4,%5,%6,%7}, {%8,%9}, {%0,%1,%2,%3};"
                 : "+f"(c[0]), "+f"(c[1]), "+f"(c[2]), "+f"(c[3])
                 : "r"(a[0]), "r"(a[1]), "r"(a[2]), "r"(a[3]), "r"(b0), "r"(b1));
}

__device__ __forceinline__ uint32_t packbf2(__nv_bfloat16 a, __nv_bfloat16 b)
{
    __nv_bfloat162 t = __halves2bfloat162(a, b);
    uint32_t u; memcpy(&u, &t, 4); return u;
}

// split a float4 into hi/lo bf16 quads, store as 8B each
__device__ __forceinline__ void split4_store(float4 v, __nv_bfloat16* hp, __nv_bfloat16* lp)
{
    __nv_bfloat16 h0 = __float2bfloat16_rn(v.x), h1 = __float2bfloat16_rn(v.y);
    __nv_bfloat16 h2 = __float2bfloat16_rn(v.z), h3 = __float2bfloat16_rn(v.w);
    __nv_bfloat16 l0 = __float2bfloat16_rn(v.x - __bfloat162float(h0));
    __nv_bfloat16 l1 = __float2bfloat16_rn(v.y - __bfloat162float(h1));
    __nv_bfloat16 l2 = __float2bfloat16_rn(v.z - __bfloat162float(h2));
    __nv_bfloat16 l3 = __float2bfloat16_rn(v.w - __bfloat162float(h3));
    uint2 hu; hu.x = packbf2(h0, h1); hu.y = packbf2(h2, h3);
    uint2 lu; lu.x = packbf2(l0, l1); lu.y = packbf2(l2, l3);
    *(uint2*)hp = hu;
    *(uint2*)lp = lu;
}

__device__ __forceinline__ void cp16(uint32_t dst, const void* src)
{
    asm volatile("cp.async.cg.shared.global [%0], [%1], 16;" :: "r"(dst), "l"(src));
}
#define CP_COMMIT() asm volatile("cp.async.commit_group;")
#define CP_WAIT_ALL() asm volatile("cp.async.wait_group 0;")

// ---------------- RMSNorm ---------------------------------------------------
__global__ __launch_bounds__(256) void rmsnorm_kernel(const float* __restrict__ x,
                                                      const float* __restrict__ w,
                                                      float* __restrict__ out)
{
    int b = blockIdx.x, t = threadIdx.x;
    const float4* x4 = (const float4*)(x + b * HID);
    const float4* w4 = (const float4*)w;
    float4* o4 = (float4*)(out + b * HID);

    float ss = 0.f;
    for (int i = t; i < HID / 4; i += 256) {
        float4 v = x4[i];
        ss += v.x * v.x + v.y * v.y + v.z * v.z + v.w * v.w;
    }
    #pragma unroll
    for (int o = 16; o; o >>= 1) ss += __shfl_xor_sync(0xffffffffu, ss, o);

    __shared__ float red[8];
    __shared__ float s_rs;
    if ((t & 31) == 0) red[t >> 5] = ss;
    __syncthreads();
    if (t == 0) {
        float tot = 0.f;
        for (int i = 0; i < 8; i++) tot += red[i];
        s_rs = rsqrtf(tot / (float)HID + 1e-6f);
    }
    __syncthreads();
    float rs = s_rs;
    for (int i = t; i < HID / 4; i += 256) {
        float4 v = x4[i], ww = w4[i];
        float4 o;
        o.x = v.x * rs * ww.x; o.y = v.y * rs * ww.y;
        o.z = v.z * rs * ww.z; o.w = v.w * rs * ww.w;
        o4[i] = o;
    }
}

// ---------------- split-bf16 3-pass ldmatrix MMA GEMM (NTILE=64, verified) --
// W selected per-block for fused QKV (Wk/Wv passed null for plain GEMMs).
__global__ __launch_bounds__(256, 1) void mma_gemm64(const float* __restrict__ A,
                                                     const float* __restrict__ W,
                                                     const float* __restrict__ Wk2,
                                                     const float* __restrict__ Wv2,
                                                     float* __restrict__ out,
                                                     int N, int K, int Kchunk)
{
    constexpr int ROW  = 40;
    constexpr int ABUF = 64 * ROW * 2;

    extern __shared__ __align__(16) char dynsm[];
    __nv_bfloat16* Ah = (__nv_bfloat16*)dynsm;            // [2][64][ROW]
    __nv_bfloat16* Al = Ah + 2 * 64 * ROW;
    __nv_bfloat16* Bh = Al + 2 * 64 * ROW;                // [2][64][ROW]
    __nv_bfloat16* Bl = Bh + 2 * 64 * ROW;

    const int t    = threadIdx.x;
    const int nb   = blockIdx.x * 64;
    const int koff = blockIdx.y * Kchunk;
    const int w    = t >> 5, l = t & 31;
    const int g    = l >> 2, tg = l & 3;
    const int mh   = w & 1, nq = w >> 1;
    const int grp  = l >> 3, rr = l & 7;

    // fused-QKV weight select: cols [0,3584) Wq, [3584,4096) Wk, [4096,...) Wv
    const float* Wsel = W;
    int wn = nb;
    if (Wk2 != nullptr && nb >= NH * HD) {
        if (nb < NH * HD + NKV * HD) { Wsel = Wk2; wn = nb - NH * HD; }
        else                          { Wsel = Wv2; wn = nb - NH * HD - NKV * HD; }
    }

    const int lr = t >> 3;
    const int lc = (t & 7) * 4;

    float acc[2][2][4];
    #pragma unroll
    for (int ms = 0; ms < 2; ms++)
        #pragma unroll
        for (int s = 0; s < 2; s++)
            #pragma unroll
            for (int i = 0; i < 4; i++) acc[ms][s][i] = 0.f;

    const uint32_t aB  = (uint32_t)__cvta_generic_to_shared(Ah);
    const uint32_t alB = (uint32_t)__cvta_generic_to_shared(Al);
    const uint32_t bB  = (uint32_t)__cvta_generic_to_shared(Bh);
    const uint32_t blB = (uint32_t)__cvta_generic_to_shared(Bl);
    const int acol = (grp >> 1) * 8;
    uint32_t aAddr[2], alAddr[2], bAddr, blAddr;
    #pragma unroll
    for (int ms = 0; ms < 2; ms++) {
        int row = mh * 32 + ms * 16 + (grp & 1) * 8 + rr;
        aAddr[ms]  = aB  + (row * ROW + acol) * 2;
        alAddr[ms] = alB + (row * ROW + acol) * 2;
    }
    {
        int row = nq * 16 + (grp & 1) * 8 + rr;
        bAddr  = bB  + (row * ROW + acol) * 2;
        blAddr = blB + (row * ROW + acol) * 2;
    }

    const float* Ap = A + koff;
    const float* Wp = Wsel + koff;
    const int niter = Kchunk / 32;

    float4 pa[2], pb[2];
    pa[0] = *(const float4*)(Ap + (size_t)lr * K + lc);
    pa[1] = *(const float4*)(Ap + (size_t)(lr + 32) * K + lc);
    pb[0] = *(const float4*)(Wp + (size_t)(wn + lr) * K + lc);
    pb[1] = *(const float4*)(Wp + (size_t)(wn + lr + 32) * K + lc);

    int cur = 0;
    for (int c = 0; c < niter; c++) {
        split4_store(pa[0], &Ah[(cur * 64 + lr) * ROW + lc],      &Al[(cur * 64 + lr) * ROW + lc]);
        split4_store(pa[1], &Ah[(cur * 64 + lr + 32) * ROW + lc], &Al[(cur * 64 + lr + 32) * ROW + lc]);
        split4_store(pb[0], &Bh[(cur * 64 + lr) * ROW + lc],      &Bl[(cur * 64 + lr) * ROW + lc]);
        split4_store(pb[1], &Bh[(cur * 64 + lr + 32) * ROW + lc], &Bl[(cur * 64 + lr + 32) * ROW + lc]);
        __syncthreads();

        if (c + 1 < niter) {
            int kb = (c + 1) * 32;
            pa[0] = *(const float4*)(Ap + (size_t)lr * K + kb + lc);
            pa[1] = *(const float4*)(Ap + (size_t)(lr + 32) * K + kb + lc);
            pb[0] = *(const float4*)(Wp + (size_t)(wn + lr) * K + kb + lc);
            pb[1] = *(const float4*)(Wp + (size_t)(wn + lr + 32) * K + kb + lc);
        }

        const uint32_t oa = cur * ABUF, ob = cur * ABUF;
        #pragma unroll
        for (int kk = 0; kk < 32; kk += 16) {
            uint32_t ah[2][4], al_[2][4];
            #pragma unroll
            for (int ms = 0; ms < 2; ms++) {
                ldsm4(ah[ms][0], ah[ms][1], ah[ms][2], ah[ms][3], aAddr[ms] + oa + kk * 2);
                ldsm4(al_[ms][0], al_[ms][1], al_[ms][2], al_[ms][3], alAddr[ms] + oa + kk * 2);
            }
            uint32_t bh[4], bl_[4];
            ldsm4(bh[0], bh[1], bh[2], bh[3], bAddr + ob + kk * 2);
            ldsm4(bl_[0], bl_[1], bl_[2], bl_[3], blAddr + ob + kk * 2);
            #pragma unroll
            for (int ms = 0; ms < 2; ms++) {
                mma16816(acc[ms][0], ah[ms],  bh[0],  bh[2]);
                mma16816(acc[ms][0], ah[ms],  bl_[0], bl_[2]);
                mma16816(acc[ms][0], al_[ms], bh[0],  bh[2]);
                mma16816(acc[ms][1], ah[ms],  bh[1],  bh[3]);
                mma16816(acc[ms][1], ah[ms],  bl_[1], bl_[3]);
                mma16816(acc[ms][1], al_[ms], bh[1],  bh[3]);
            }
        }
        cur ^= 1;
    }

    float* outp = out + (size_t)blockIdx.y * 64 * N;
    #pragma unroll
    for (int ms = 0; ms < 2; ms++) {
        #pragma unroll
        for (int s = 0; s < 2; s++) {
            const int r0 = mh * 32 + ms * 16 + g;
            const int r1 = r0 + 8;
            const int col = nb + nq * 16 + s * 8 + tg * 2;
            outp[(size_t)r0 * N + col]     = acc[ms][s][0];
            outp[(size_t)r0 * N + col + 1] = acc[ms][s][1];
            outp[(size_t)r1 * N + col]     = acc[ms][s][2];
            outp[(size_t)r1 * N + col + 1] = acc[ms][s][3];
        }
    }
}

// ---------------- fused gate+up MLP GEMM (NTILE=64 each, shared A frags) ----
__global__ __launch_bounds__(256, 1) void mlp_gateup_kernel(const float* __restrict__ A,
                                                            const float* __restrict__ Wg,
                                                            const float* __restrict__ Wu,
                                                            float* __restrict__ act,
                                                            int N, int K)
{
    constexpr int ROW  = 40;
    constexpr int ABUF = 64 * ROW * 2;

    extern __shared__ __align__(16) char dynsm[];
    __nv_bfloat16* Ah  = (__nv_bfloat16*)dynsm;           // [2][64][ROW] each
    __nv_bfloat16* Al  = Ah  + 2 * 64 * ROW;
    __nv_bfloat16* Bgh = Al  + 2 * 64 * ROW;
    __nv_bfloat16* Bgl = Bgh + 2 * 64 * ROW;
    __nv_bfloat16* Buh = Bgl + 2 * 64 * ROW;
    __nv_bfloat16* Bul = Buh + 2 * 64 * ROW;

    const int t  = threadIdx.x;
    const int nb = blockIdx.x * 64;
    const int w  = t >> 5, l = t & 31;
    const int g  = l >> 2, tg = l & 3;
    const int mh = w & 1, nq = w >> 1;
    const int grp = l >> 3, rr = l & 7;

    const int lr = t >> 3;
    const int lc = (t & 7) * 4;

    float accg[2][2][4], accu[2][2][4];
    #pragma unroll
    for (int ms = 0; ms < 2; ms++)
        #pragma unroll
        for (int s = 0; s < 2; s++)
            #pragma unroll
            for (int i = 0; i < 4; i++) { accg[ms][s][i] = 0.f; accu[ms][s][i] = 0.f; }

    const uint32_t aB   = (uint32_t)__cvta_generic_to_shared(Ah);
    const uint32_t alB  = (uint32_t)__cvta_generic_to_shared(Al);
    const uint32_t bgB  = (uint32_t)__cvta_generic_to_shared(Bgh);
    const uint32_t bglB = (uint32_t)__cvta_generic_to_shared(Bgl);
    const uint32_t buB  = (uint32_t)__cvta_generic_to_shared(Buh);
    const uint32_t bulB = (uint32_t)__cvta_generic_to_shared(Bul);
    const int acol = (grp >> 1) * 8;
    uint32_t aAddr[2], alAddr[2], bgA, bglA, buA, bulA;
    #pragma unroll
    for (int ms = 0; ms < 2; ms++) {
        int row = mh * 32 + ms * 16 + (grp & 1) * 8 + rr;
        aAddr[ms]  = aB  + (row * ROW + acol) * 2;
        alAddr[ms] = alB + (row * ROW + acol) * 2;
    }
    {
        int row = nq * 16 + (grp & 1) * 8 + rr;
        bgA  = bgB  + (row * ROW + acol) * 2;
        bglA = bglB + (row * ROW + acol) * 2;
        buA  = buB  + (row * ROW + acol) * 2;
        bulA = bulB + (row * ROW + acol) * 2;
    }

    const int niter = K / 32;

    float4 pa[2], pg[2], pu[2];
    pa[0] = *(const float4*)(A + (size_t)lr * K + lc);
    pa[1] = *(const float4*)(A + (size_t)(lr + 32) * K + lc);
    pg[0] = *(const float4*)(Wg + (size_t)(nb + lr) * K + lc);
    pg[1] = *(const float4*)(Wg + (size_t)(nb + lr + 32) * K + lc);
    pu[0] = *(const float4*)(Wu + (size_t)(nb + lr) * K + lc);
    pu[1] = *(const float4*)(Wu + (size_t)(nb + lr + 32) * K + lc);

    int cur = 0;
    for (int c = 0; c < niter; c++) {
        split4_store(pa[0], &Ah[(cur * 64 + lr) * ROW + lc],       &Al[(cur * 64 + lr) * ROW + lc]);
        split4_store(pa[1], &Ah[(cur * 64 + lr + 32) * ROW + lc],  &Al[(cur * 64 + lr + 32) * ROW + lc]);
        split4_store(pg[0], &Bgh[(cur * 64 + lr) * ROW + lc],      &Bgl[(cur * 64 + lr) * ROW + lc]);
        split4_store(pg[1], &Bgh[(cur * 64 + lr + 32) * ROW + lc], &Bgl[(cur * 64 + lr + 32) * ROW + lc]);
        split4_store(pu[0], &Buh[(cur * 64 + lr) * ROW + lc],      &Bul[(cur * 64 + lr) * ROW + lc]);
        split4_store(pu[1], &Buh[(cur * 64 + lr + 32) * ROW + lc], &Bul[(cur * 64 + lr + 32) * ROW + lc]);
        __syncthreads();

        if (c + 1 < niter) {
            int kb = (c + 1) * 32;
            pa[0] = *(const float4*)(A + (size_t)lr * K + kb + lc);
            pa[1] = *(const float4*)(A + (size_t)(lr + 32) * K + kb + lc);
            pg[0] = *(const float4*)(Wg + (size_t)(nb + lr) * K + kb + lc);
            pg[1] = *(const float4*)(Wg + (size_t)(nb + lr + 32) * K + kb + lc);
            pu[0] = *(const float4*)(Wu + (size_t)(nb + lr) * K + kb + lc);
            pu[1] = *(const float4*)(Wu + (size_t)(nb + lr + 32) * K + kb + lc);
        }

        const uint32_t off = cur * ABUF;
        #pragma unroll
        for (int kk = 0; kk < 32; kk += 16) {
            uint32_t ah[2][4], al_[2][4];
            #pragma unroll
            for (int ms = 0; ms < 2; ms++) {
                ldsm4(ah[ms][0], ah[ms][1], ah[ms][2], ah[ms][3], aAddr[ms] + off + kk * 2);
                ldsm4(al_[ms][0], al_[ms][1], al_[ms][2], al_[ms][3], alAddr[ms] + off + kk * 2);
            }
            uint32_t gh[4], gl[4], uh[4], ul[4];
            ldsm4(gh[0], gh[1], gh[2], gh[3], bgA  + off + kk * 2);
            ldsm4(gl[0], gl[1], gl[2], gl[3], bglA + off + kk * 2);
            ldsm4(uh[0], uh[1], uh[2], uh[3], buA  + off + kk * 2);
            ldsm4(ul[0], ul[1], ul[2], ul[3], bulA + off + kk * 2);
            #pragma unroll
            for (int ms = 0; ms < 2; ms++) {
                mma16816(accg[ms][0], ah[ms],  gh[0], gh[2]);
                mma16816(accg[ms][0], ah[ms],  gl[0], gl[2]);
                mma16816(accg[ms][0], al_[ms], gh[0], gh[2]);
                mma16816(accg[ms][1], ah[ms],  gh[1], gh[3]);
                mma16816(accg[ms][1], ah[ms],  gl[1], gl[3]);
                mma16816(accg[ms][1], al_[ms], gh[1], gh[3]);
                mma16816(accu[ms][0], ah[ms],  uh[0], uh[2]);
                mma16816(accu[ms][0], ah[ms],  ul[0], ul[2]);
                mma16816(accu[ms][0], al_[ms], uh[0], uh[2]);
                mma16816(accu[ms][1], ah[ms],  uh[1], uh[3]);
                mma16816(accu[ms][1], ah[ms],  ul[1], ul[3]);
                mma16816(accu[ms][1], al_[ms], uh[1], uh[3]);
            }
        }
        cur ^= 1;
    }

    #pragma unroll
    for (int ms = 0; ms < 2; ms++) {
        #pragma unroll
        for (int s = 0; s < 2; s++) {
            const int r0 = mh * 32 + ms * 16 + g;
            const int r1 = r0 + 8;
            const int col = nb + nq * 16 + s * 8 + tg * 2;
            const int rws[4] = {r0, r0, r1, r1};
            const int cls[4] = {col, col + 1, col, col + 1};
            #pragma unroll
            for (int i = 0; i < 4; i++) {
                float gv = accg[ms][s][i];
                float uv = accu[ms][s][i];
                act[(size_t)rws[i] * N + cls[i]] = uv * (gv / (1.f + expf(-gv)));
            }
        }
    }
}

// ---------------- split-K reduces -------------------------------------------
enum { RED_RESID = 2 };

template<int SK, int MODE>
__global__ __launch_bounds__(256) void reduce_kernel(const float* __restrict__ part,
                                                     const float* __restrict__ extra,
                                                     float* __restrict__ out,
                                                     int total, int N)
{
    int i = blockIdx.x * 256 + threadIdx.x;
    if (i >= total) return;
    float s = 0.f;
    #pragma unroll
    for (int k = 0; k < SK; k++) s += part[(size_t)k * total + i];
    if constexpr (MODE == RED_RESID) s += extra[i];
    out[i] = s;
}

// QKV reduce: sum 8 partials, add per-section bias, scatter to q/k/v buffers
__global__ __launch_bounds__(256) void reduce_qkv_kernel(const float* __restrict__ part,
                                                         const float* __restrict__ bq,
                                                         const float* __restrict__ bk,
                                                         const float* __restrict__ bv,
                                                         float* __restrict__ q,
                                                         float* __restrict__ k,
                                                         float* __restrict__ v)
{
    const int total = BS * QKVN;
    int i = blockIdx.x * 256 + threadIdx.x;
    if (i >= total) return;
    float s = 0.f;
    #pragma unroll
    for (int p = 0; p < 8; p++) s += part[(size_t)p * total + i];
    int b = i / QKVN, col = i % QKVN;
    if (col < NH * HD)                 q[b * NH * HD + col] = s + bq[col];
    else if (col < NH * HD + NKV * HD) k[b * NKV * HD + col - NH * HD] = s + bk[col - NH * HD];
    else                               v[b * NKV * HD + col - NH * HD - NKV * HD] = s + bv[col - NH * HD - NKV * HD];
}

// ---------------- RoPE (double-precision angles) ----------------------------
__global__ __launch_bounds__(256) void rope_kernel(float* __restrict__ q,
                                                   const float* __restrict__ k,
                                                   const float* __restrict__ v,
                                                   const int* __restrict__ positions,
                                                   float* __restrict__ knew,
                                                   float* __restrict__ vnew)
{
    int b = blockIdx.x, t = threadIdx.x;
    double pos = (double)positions[b];
    const double L = 13.815510557964274104107948728106; // ln(1e6)

    for (int i = t; i < NH * 64; i += 256) {
        int h = i >> 6, d = i & 63;
        double inv = exp(-(double)(2 * d) * (1.0 / HD) * L);
        double cd, sd; sincos(pos * inv, &cd, &sd);
        float c = (float)cd, s = (float)sd;
        float* base = q + b * NH * HD + h * HD + d;
        float t1 = base[0], t2 = base[64];
        base[0]  = t1 * c - t2 * s;
        base[64] = t2 * c + t1 * s;
    }
    for (int i = t; i < NKV * 64; i += 256) {
        int h = i >> 6, d = i & 63;
        double inv = exp(-(double)(2 * d) * (1.0 / HD) * L);
        double cd, sd; sincos(pos * inv, &cd, &sd);
        float c = (float)cd, s = (float)sd;
        const float* src = k + b * NKV * HD + h * HD + d;
        float t1 = src[0], t2 = src[64];
        float* dst = knew + b * NKV * HD + h * HD + d;
        dst[0]  = t1 * c - t2 * s;
        dst[64] = t2 * c + t1 * s;
    }
    for (int i = t; i < NKV * HD; i += 256)
        vnew[b * NKV * HD + i] = v[b * NKV * HD + i];
}

// ---------------- Paged attention (KV-split x4, online softmax) -------------
__global__ __launch_bounds__(256, 1) void attn_kernel(const float* __restrict__ kc,
                                                      const float* __restrict__ vc,
                                                      const int* __restrict__ block_tables,
                                                      const int* __restrict__ seq_lens,
                                                      const float* __restrict__ qbuf,
                                                      const float* __restrict__ knew,
                                                      const float* __restrict__ vnew,
                                                      float* __restrict__ partP,
                                                      float* __restrict__ partM,
                                                      float* __restrict__ partL)
{
    const int kvh = blockIdx.x, b = blockIdx.y, split = blockIdx.z;
    const int t = threadIdx.x;
    const int seq = seq_lens[b];
    const int pos = seq - 1;

    const int ntiles = (seq + 31) >> 5;
    const int quarter = (ntiles + NSPL - 1) / NSPL;
    const int t0 = split * quarter;
    const int t1 = min(ntiles, t0 + quarter);

    extern __shared__ __align__(16) char dynsm[];
    float* q_s = (float*)dynsm;                 // [GROUP][HD]
    float* k_s = q_s + GROUP * HD;              // [2][32][132]
    float* v_s = k_s + 2 * 32 * 132;            // [2][32][132]
    __shared__ int bt_s[MAX_BLOCKS];
    __shared__ float p_s[GROUP][32];
    __shared__ float m_s[GROUP], l_s[GROUP], sc_s[GROUP];

    const uint32_t kBase = (uint32_t)__cvta_generic_to_shared(k_s);
    const uint32_t vBase = (uint32_t)__cvta_generic_to_shared(v_s);

    for (int i = t; i < MAX_BLOCKS; i += 256) bt_s[i] = block_tables[b * MAX_BLOCKS + i];
    for (int i = t; i < GROUP * HD; i += 256)
        q_s[i] = qbuf[b * NH * HD + kvh * GROUP * HD + i];
    if (t < GROUP) { m_s[t] = -1e30f; l_s[t] = 0.f; }
    __syncthreads();

    const int w = t >> 5, lane = t & 31;
    const int hh = lane >> 2, dq = lane & 3;
    const int hsel = hh < GROUP ? hh : GROUP - 1;
    const int dpv = w * 16 + dq * 4;
    float acc[4] = {0.f, 0.f, 0.f, 0.f};

    auto issue_tile = [&](int tile, int buf) {
        const int tbase = tile << 5;
        #pragma unroll
        for (int j = 0; j < 4; j++) {
            int i = t + 256 * j;
            int tt = i >> 5, d4 = (i & 31) << 2;
            int tok = tbase + tt;
            const float *ksrc, *vsrc;
            if (tok == pos) {
                int off = b * NKV * HD + kvh * HD + d4;
                ksrc = knew + off; vsrc = vnew + off;
            } else {
                int blk = bt_s[tok >> 4];
                int base = ((blk << 4) + (tok & 15)) * (NKV * HD) + kvh * HD + d4;
                ksrc = kc + base; vsrc = vc + base;
            }
            uint32_t soff = ((buf * 32 + tt) * 132 + d4) * 4;
            cp16(kBase + soff, ksrc);
            cp16(vBase + soff, vsrc);
        }
        CP_COMMIT();
    };

    if (t0 < t1) issue_tile(t0, 0);
    int cur = 0;

    for (int tile = t0; tile < t1; tile++) {
        CP_WAIT_ALL();
        __syncthreads();
        if (tile + 1 < t1) issue_tile(tile + 1, cur ^ 1);

        const int tbase = tile << 5;
        const float* kb = k_s + cur * 32 * 132;
        const float* vb = v_s + cur * 32 * 132;

        if (w < GROUP) {
            float sc = 0.f;
            #pragma unroll
            for (int d4 = 0; d4 < HD; d4 += 4) {
                float4 qv = *(const float4*)&q_s[w * HD + d4];
                float4 kv = *(const float4*)&kb[lane * 132 + d4];
                sc = fmaf(qv.x, kv.x, sc); sc = fmaf(qv.y, kv.y, sc);
                sc = fmaf(qv.z, kv.z, sc); sc = fmaf(qv.w, kv.w, sc);
            }
            sc *= 0.08838834764831845f;            // HD^-0.5
            if (tbase + lane >= seq) sc = -1e30f;

            float mx = sc;
            #pragma unroll
            for (int o = 16; o; o >>= 1) mx = fmaxf(mx, __shfl_xor_sync(0xffffffffu, mx, o));
            float m_old = m_s[w];
            float m_new = fmaxf(m_old, mx);
            float p = expf(sc - m_new);
            p_s[w][lane] = p;
            float sum = p;
            #pragma unroll
            for (int o = 16; o; o >>= 1) sum += __shfl_xor_sync(0xffffffffu, sum, o);
            if (lane == 0) {
                float scl = expf(m_old - m_new);
                sc_s[w] = scl;
                l_s[w] = l_s[w] * scl + sum;
                m_s[w] = m_new;
            }
        }
        __syncthreads();

        // P.V: all 8 warps; V tile read exactly once across the CTA
        {
            float scl = sc_s[hsel];
            acc[0] *= scl; acc[1] *= scl; acc[2] *= scl; acc[3] *= scl;
            #pragma unroll 8
            for (int tt = 0; tt < 32; tt++) {
                float p = p_s[hsel][tt];
                float4 v4 = *(const float4*)&vb[tt * 132 + dpv];
                acc[0] = fmaf(p, v4.x, acc[0]);
                acc[1] = fmaf(p, v4.y, acc[1]);
                acc[2] = fmaf(p, v4.z, acc[2]);
                acc[3] = fmaf(p, v4.w, acc[3]);
            }
        }
        __syncthreads();
        cur ^= 1;
    }

    if (hh < GROUP) {
        size_t base = ((((size_t)split * BS + b) * NKV + kvh) * GROUP + hh) * HD + dpv;
        float4 o; o.x = acc[0]; o.y = acc[1]; o.z = acc[2]; o.w = acc[3];
        *(float4*)(partP + base) = o;
        if (w == 0 && dq == 0) {
            size_t mlb = (((size_t)split * BS + b) * NKV + kvh) * GROUP + hh;
            partM[mlb] = m_s[hh];
            partL[mlb] = l_s[hh];
        }
    }
}

// merge the NSPL KV splits
__global__ __launch_bounds__(256) void attn_merge_kernel(const float* __restrict__ partP,
                                                         const float* __restrict__ partM,
                                                         const float* __restrict__ partL,
                                                         float* __restrict__ attn_out)
{
    const int total = BS * NKV * GROUP * HD;
    const int mltot = total / HD;
    int i = blockIdx.x * 256 + threadIdx.x;
    if (i >= total) return;
    int ml = i >> 7;
    int d  = i & 127;
    float m[NSPL], M = -1e30f;
    #pragma unroll
    for (int s = 0; s < NSPL; s++) { m[s] = partM[(size_t)s * mltot + ml]; M = fmaxf(M, m[s]); }
    float num = 0.f, den = 0.f;
    #pragma unroll
    for (int s = 0; s < NSPL; s++) {
        float ws = expf(m[s] - M);
        num += partP[(size_t)s * total + i] * ws;
        den += partL[(size_t)s * mltot + ml] * ws;
    }
    int b = ml / (NKV * GROUP);
    int rest = ml % (NKV * GROUP);   // kvh*GROUP + hh == head index
    attn_out[((size_t)b * NH + rest) * HD + d] = num / den;
}

// ---------------- launch ----------------------------------------------------
extern "C" void kernel_launch(void* const* d_in, const int* in_sizes, int n_in,
                              void* d_out, int out_size)
{
    const float* x            = (const float*)d_in[0];
    const int*   positions    = (const int*)  d_in[1];
    const float* k_cache      = (const float*)d_in[2];
    const float* v_cache      = (const float*)d_in[3];
    const int*   block_tables = (const int*)  d_in[4];
    const int*   seq_lens     = (const int*)  d_in[5];
    /* d_in[6] slot_mapping: unused (pos == seq_len-1 substitution instead) */
    const float* in_w   = (const float*)d_in[7];
    const float* post_w = (const float*)d_in[8];
    const float* Wq = (const float*)d_in[9];
    const float* bq = (const float*)d_in[10];
    const float* Wk = (const float*)d_in[11];
    const float* bk = (const float*)d_in[12];
    const float* Wv = (const float*)d_in[13];
    const float* bv = (const float*)d_in[14];
    const float* Wo = (const float*)d_in[15];
    const float* Wg = (const float*)d_in[16];
    const float* Wu = (const float*)d_in[17];
    const float* Wd = (const float*)d_in[18];
    float* out = (float*)d_out;

    float *p_h, *p_q, *p_k, *p_v, *p_kn, *p_vn, *p_attn, *p_hidden, *p_h2, *p_act;
    float *pQKV, *pO, *pD, *aP, *aM, *aL;
    cudaGetSymbolAddress((void**)&p_h,      g_h);
    cudaGetSymbolAddress((void**)&p_q,      g_q);
    cudaGetSymbolAddress((void**)&p_k,      g_k);
    cudaGetSymbolAddress((void**)&p_v,      g_v);
    cudaGetSymbolAddress((void**)&p_kn,     g_knew);
    cudaGetSymbolAddress((void**)&p_vn,     g_vnew);
    cudaGetSymbolAddress((void**)&p_attn,   g_attn);
    cudaGetSymbolAddress((void**)&p_hidden, g_hidden);
    cudaGetSymbolAddress((void**)&p_h2,     g_h2);
    cudaGetSymbolAddress((void**)&p_act,    g_act);
    cudaGetSymbolAddress((void**)&pQKV, g_pQKV);
    cudaGetSymbolAddress((void**)&pO, g_pO);
    cudaGetSymbolAddress((void**)&pD, g_pD);
    cudaGetSymbolAddress((void**)&aP, g_attP);
    cudaGetSymbolAddress((void**)&aM, g_attM);
    cudaGetSymbolAddress((void**)&aL, g_attL);

    constexpr int SM64  = 2 * (64 + 64 + 64 + 64) * 40 * 2;             // 40960
    constexpr int SMGU  = 2 * (64 + 64 + 64 + 64 + 64 + 64) * 40 * 2;   // 61440
    constexpr int SMATT = (GROUP * HD + 4 * 32 * 132) * 4;              // 71168

    cudaFuncSetAttribute(mma_gemm64,        cudaFuncAttributeMaxDynamicSharedMemorySize, SM64);
    cudaFuncSetAttribute(mlp_gateup_kernel, cudaFuncAttributeMaxDynamicSharedMemorySize, SMGU);
    cudaFuncSetAttribute(attn_kernel,       cudaFuncAttributeMaxDynamicSharedMemorySize, SMATT);

    rmsnorm_kernel<<<BS, 256>>>(x, in_w, p_h);

    // fused QKV projection (one launch, grid 72x8, split-K 8)
    mma_gemm64<<<dim3(QKVN / 64, 8), 256, SM64>>>(p_h, Wq, Wk, Wv, pQKV, QKVN, HID, HID / 8);
    reduce_qkv_kernel<<<(BS * QKVN) / 256, 256>>>(pQKV, bq, bk, bv, p_q, p_k, p_v);

    rope_kernel<<<BS, 256>>>(p_q, p_k, p_v, positions, p_kn, p_vn);

    attn_kernel<<<dim3(NKV, BS, NSPL), 256, SMATT>>>(k_cache, v_cache, block_tables, seq_lens,
                                                     p_q, p_kn, p_vn, aP, aM, aL);
    attn_merge_kernel<<<(BS * NKV * GROUP * HD) / 256, 256>>>(aP, aM, aL, p_attn);

    // O projection (NTILE=64, split-K 8) + residual
    mma_gemm64<<<dim3(HID / 64, 8), 256, SM64>>>(p_attn, Wo, nullptr, nullptr, pO, HID, NH * HD, (NH * HD) / 8);
    reduce_kernel<8, RED_RESID><<<(BS * HID) / 256, 256>>>(pO, x, p_hidden, BS * HID, HID);

    rmsnorm_kernel<<<BS, 256>>>(p_hidden, post_w, p_h2);

    // fused gate+up MLP (grid 296; shared A fragments; silu in-register)
    mlp_gateup_kernel<<<INTER / 64, 256, SMGU>>>(p_h2, Wg, Wu, p_act, INTER, HID);

    // down projection (NTILE=64, split-K 8) + residual
    mma_gemm64<<<dim3(HID / 64, 8), 256, SM64>>>(p_act, Wd, nullptr, nullptr, pD, HID, INTER, INTER / 8);
    reduce_kernel<8, RED_RESID><<<(BS * HID) / 256, 256>>>(pD, p_hidden, out, BS * HID, HID);
}